// round 9
// baseline (speedup 1.0000x reference)
#include <cuda_runtime.h>
#include <cuda_bf16.h>
#include <math.h>
#include <stdint.h>

#define NN 10000
#define NP 10176            // 106 * 96
#define EE 160000
#define HH 512
#define CC 10
#define MM (HH * HH)
#define BN_EPS 1e-5f

// ---------------- device scratch ----------------
__device__ float g_h1[NP * HH];      // raw relu(conv) output (pre-BN)
__device__ float g_h2[NP * HH];
__device__ float g_agg[NP * HH];
__device__ __nv_bfloat16 g_xh[NP * HH], g_xl[NP * HH];
__device__ __nv_bfloat16 g_hh1[NP * HH], g_hl1[NP * HH];   // z splits ping
__device__ __nv_bfloat16 g_hh2[NP * HH], g_hl2[NP * HH];   // z splits pong
__device__ __nv_bfloat16 g_ah[NP * HH], g_al[NP * HH];
__device__ __nv_bfloat16 g_wh[2 * MM], g_wl[2 * MM];       // proj weights (unscaled)
__device__ __nv_bfloat16 g_fwh[2 * MM], g_fwl[2 * MM];     // folded layer weights
__device__ float g_bias[HH];
__device__ float g_scale[NN];
__device__ int   g_degi[NN];
__device__ int   g_rowptr[NN + 1];
__device__ int   g_fill[NN];
__device__ int   g_esrc[EE];
__device__ float g_sum[HH];
__device__ float g_sq[HH];
__device__ float g_bnA[HH];
__device__ float g_bnB[HH];

// ---------------- PTX helpers ----------------
__device__ __forceinline__ uint32_t cvta_s(const void* p) {
    return (uint32_t)__cvta_generic_to_shared(p);
}
__device__ __forceinline__ void cpa16(uint32_t dst, const void* src) {
    asm volatile("cp.async.cg.shared.global [%0], [%1], 16;\n" :: "r"(dst), "l"(src));
}
__device__ __forceinline__ void ldm_x4(uint32_t& r0, uint32_t& r1, uint32_t& r2, uint32_t& r3, uint32_t addr) {
    asm volatile("ldmatrix.sync.aligned.m8n8.x4.shared.b16 {%0,%1,%2,%3}, [%4];\n"
                 : "=r"(r0), "=r"(r1), "=r"(r2), "=r"(r3) : "r"(addr));
}
__device__ __forceinline__ void mma_bf16(float* d, uint32_t a0, uint32_t a1, uint32_t a2, uint32_t a3,
                                         uint32_t b0, uint32_t b1) {
    asm volatile("mma.sync.aligned.m16n8k16.row.col.f32.bf16.bf16.f32 "
                 "{%0,%1,%2,%3}, {%4,%5,%6,%7}, {%8,%9}, {%0,%1,%2,%3};\n"
                 : "+f"(d[0]), "+f"(d[1]), "+f"(d[2]), "+f"(d[3])
                 : "r"(a0), "r"(a1), "r"(a2), "r"(a3), "r"(b0), "r"(b1));
}

// ---------------- fused prep ----------------
#define SPLITX (NN * HH)
#define SPLITW (2 * MM)
#define PADSZ  ((NP - NN) * HH)
#define PREP_TOTAL (SPLITX + SPLITW + PADSZ + NN + HH)

__global__ void k_prep(const float* __restrict__ x,
                       const float* __restrict__ Wpr, const float* __restrict__ Wpw) {
    int i = blockIdx.x * blockDim.x + threadIdx.x;
    if (i < SPLITX) {
        float v = x[i];
        __nv_bfloat16 h = __float2bfloat16(v);
        g_xh[i] = h;
        g_xl[i] = __float2bfloat16(v - __bfloat162float(h));
        return;
    }
    i -= SPLITX;
    if (i < SPLITW) {
        int w = i >> 18;
        int off = i & (MM - 1);
        float v = w ? Wpw[off] : Wpr[off];
        __nv_bfloat16 h = __float2bfloat16(v);
        g_wh[i] = h;
        g_wl[i] = __float2bfloat16(v - __bfloat162float(h));
        return;
    }
    i -= SPLITW;
    if (i < PADSZ) {
        int off = NN * HH + i;
        __nv_bfloat16 z = __float2bfloat16(0.0f);
        g_xh[off] = z; g_xl[off] = z;
        g_hh1[off] = z; g_hl1[off] = z;
        g_hh2[off] = z; g_hl2[off] = z;
        g_ah[off] = z; g_al[off] = z;
        return;
    }
    i -= PADSZ;
    if (i < NN) { g_degi[i] = 0; g_fill[i] = 0; return; }
    i -= NN;
    if (i < HH) { g_sum[i] = 0.f; g_sq[i] = 0.f; }
}

// ---------------- CSR build ----------------
__global__ void k_deg(const int* __restrict__ ei) {
    int e = blockIdx.x * blockDim.x + threadIdx.x;
    if (e < EE) atomicAdd(&g_degi[ei[EE + e]], 1);
}
// scan via warp shuffles (4 barriers per 1024-chunk)
__global__ void k_scanscale() {
    __shared__ int warp_part[32];
    __shared__ int carry;
    int t = threadIdx.x;
    int lane = t & 31, w = t >> 5;
    if (t == 0) carry = 0;
    __syncthreads();
    for (int base = 0; base < NN; base += 1024) {
        int i = base + t;
        int v = (i < NN) ? g_degi[i] : 0;
        if (i < NN) g_scale[i] = 1.0f / (float)(v > 0 ? v : 1);
        int s = v;
#pragma unroll
        for (int o = 1; o < 32; o <<= 1) {
            int u = __shfl_up_sync(0xffffffff, s, o);
            if (lane >= o) s += u;
        }
        if (lane == 31) warp_part[w] = s;
        __syncthreads();
        if (w == 0) {
            int p = warp_part[lane];
#pragma unroll
            for (int o = 1; o < 32; o <<= 1) {
                int u = __shfl_up_sync(0xffffffff, p, o);
                if (lane >= o) p += u;
            }
            warp_part[lane] = p;
        }
        __syncthreads();
        int add = (w > 0) ? warp_part[w - 1] : 0;
        int inc = s + add + carry;
        if (i < NN) g_rowptr[i + 1] = inc;
        __syncthreads();
        if (t == 1023) carry = inc;
        __syncthreads();
    }
    if (t == 0) g_rowptr[0] = 0;
}
__global__ void k_fill(const int* __restrict__ ei) {
    int e = blockIdx.x * blockDim.x + threadIdx.x;
    if (e < EE) {
        int dst = ei[EE + e];
        int pos = g_rowptr[dst] + atomicAdd(&g_fill[dst], 1);
        g_esrc[pos] = ei[e];
    }
}

// ---------------- mean aggregation + optional BN affine + bf16 split ----------------
__global__ void k_agg2(const float* __restrict__ h, int useBN,
                       __nv_bfloat16* __restrict__ oh, __nv_bfloat16* __restrict__ ol,
                       float* __restrict__ of) {
    int node = blockIdx.x;
    int t = threadIdx.x;
    int s = g_rowptr[node];
    int e = g_rowptr[node + 1];
    float ax = 0.f, ay = 0.f, az = 0.f, aw = 0.f;
    int j = s;
    for (; j + 1 < e; j += 2) {
        int s0 = g_esrc[j];
        int s1 = g_esrc[j + 1];
        float4 v0 = ((const float4*)(h + (size_t)s0 * HH))[t];
        float4 v1 = ((const float4*)(h + (size_t)s1 * HH))[t];
        ax += v0.x + v1.x; ay += v0.y + v1.y;
        az += v0.z + v1.z; aw += v0.w + v1.w;
    }
    if (j < e) {
        int s0 = g_esrc[j];
        float4 v0 = ((const float4*)(h + (size_t)s0 * HH))[t];
        ax += v0.x; ay += v0.y; az += v0.z; aw += v0.w;
    }
    float sc = g_scale[node];
    ax *= sc; ay *= sc; az *= sc; aw *= sc;
    if (useBN) {
        float4 a = ((const float4*)g_bnA)[t];
        float4 b = ((const float4*)g_bnB)[t];
        ax = ax * a.x + b.x; ay = ay * a.y + b.y;
        az = az * a.z + b.z; aw = aw * a.w + b.w;
    }
    if (of) {
        ((float4*)(of + (size_t)node * HH))[t] = make_float4(ax, ay, az, aw);
    }
    if (oh) {
        __nv_bfloat16 hx = __float2bfloat16(ax), hy = __float2bfloat16(ay);
        __nv_bfloat16 hz = __float2bfloat16(az), hw = __float2bfloat16(aw);
        __nv_bfloat16 lx = __float2bfloat16(ax - __bfloat162float(hx));
        __nv_bfloat16 ly = __float2bfloat16(ay - __bfloat162float(hy));
        __nv_bfloat16 lz = __float2bfloat16(az - __bfloat162float(hz));
        __nv_bfloat16 lw = __float2bfloat16(aw - __bfloat162float(hw));
        __nv_bfloat162* ph = (__nv_bfloat162*)(oh + (size_t)node * HH);
        __nv_bfloat162* pl = (__nv_bfloat162*)(ol + (size_t)node * HH);
        ph[t * 2 + 0] = __nv_bfloat162(hx, hy);
        ph[t * 2 + 1] = __nv_bfloat162(hz, hw);
        pl[t * 2 + 0] = __nv_bfloat162(lx, ly);
        pl[t * 2 + 1] = __nv_bfloat162(lz, lw);
    }
}

// ---------------- BN finalize + weight fold ----------------
__global__ void k_bnfin(const float* __restrict__ gamma, const float* __restrict__ beta) {
    int f = threadIdx.x;
    float s = g_sum[f];
    float q = g_sq[f];
    g_sum[f] = 0.f;
    g_sq[f] = 0.f;
    float mu = s / (float)NN;
    float var = q / (float)NN - mu * mu;
    float inv = rsqrtf(var + BN_EPS);
    float sc = gamma[f] * inv;
    g_bnA[f] = sc;
    g_bnB[f] = beta[f] - mu * sc;
}
// fold BN scale into layer weights + compute bias c = (Wr+Ww) @ bnB
__global__ void k_fold(const float* __restrict__ Wr, const float* __restrict__ Ww) {
    int b = blockIdx.x;
    if (b < 2048) {
        int idx = b * 256 + threadIdx.x;        // 0 .. 2*MM-1
        int off = idx & (MM - 1);
        int k = off & (HH - 1);
        float v = ((idx >> 18) ? Ww[off] : Wr[off]) * g_bnA[k];
        __nv_bfloat16 h = __float2bfloat16(v);
        g_fwh[idx] = h;
        g_fwl[idx] = __float2bfloat16(v - __bfloat162float(h));
    } else {
        int o = (b - 2048) * 256 + threadIdx.x;  // 0..511
        float s = 0.f;
        for (int k = 0; k < HH; k++)
            s += (Wr[o * HH + k] + Ww[o * HH + k]) * g_bnB[k];
        g_bias[o] = s;
    }
}

// ---------------- mma.sync dual GEMM, 96x128 tile, BK=32, bias + splits + stats ----
#define LDS 40
#define A_HALVES (96 * LDS)
#define B_HALVES (128 * LDS)
#define STAGE_HALVES (2 * A_HALVES + 2 * B_HALVES)
#define GEMM_SMEM (2 * STAGE_HALVES * 2)

__global__ __launch_bounds__(192, 3)
void k_gemm6(const __nv_bfloat16* __restrict__ a1h, const __nv_bfloat16* __restrict__ a1l,
             const __nv_bfloat16* __restrict__ a2h, const __nv_bfloat16* __restrict__ a2l,
             const __nv_bfloat16* __restrict__ w1h, const __nv_bfloat16* __restrict__ w1l,
             const __nv_bfloat16* __restrict__ w2h, const __nv_bfloat16* __restrict__ w2l,
             const float* __restrict__ bias,
             float* __restrict__ C,
             __nv_bfloat16* __restrict__ oh, __nv_bfloat16* __restrict__ ol) {
    extern __shared__ __nv_bfloat16 dsm[];

    const int tx = threadIdx.x;
    const int lane = tx & 31;
    const int warp = tx >> 5;
    const int wm = (warp % 3) * 32;
    const int wn = (warp / 3) * 64;
    const int m0 = blockIdx.y * 96;
    const int n0 = blockIdx.x * 128;

    float acc[2][8][4];
#pragma unroll
    for (int i = 0; i < 2; i++)
#pragma unroll
        for (int j = 0; j < 8; j++)
#pragma unroll
            for (int q = 0; q < 4; q++) acc[i][j][q] = 0.f;

    const int NK = 32;

    auto loadStage = [&](int kt, int st) {
        const __nv_bfloat16* Ah = (kt < 16) ? a1h : a2h;
        const __nv_bfloat16* Al = (kt < 16) ? a1l : a2l;
        const __nv_bfloat16* Wh = (kt < 16) ? w1h : w2h;
        const __nv_bfloat16* Wl = (kt < 16) ? w1l : w2l;
        int k0 = (kt & 15) * 32;
        __nv_bfloat16* base = dsm + st * STAGE_HALVES;
#pragma unroll
        for (int rep = 0; rep < 2; rep++) {
            int idx = tx + rep * 192;
            int row = idx >> 2;
            int seg = (idx & 3) * 8;
            size_t ao = (size_t)(m0 + row) * HH + k0 + seg;
            uint32_t so = (uint32_t)(row * LDS + seg);
            cpa16(cvta_s(base + so), Ah + ao);
            cpa16(cvta_s(base + A_HALVES + so), Al + ao);
        }
#pragma unroll
        for (int rep = 0; rep < 3; rep++) {
            int idx = tx + rep * 192;
            if (idx < 512) {
                int row = idx >> 2;
                int seg = (idx & 3) * 8;
                size_t wo = (size_t)(n0 + row) * HH + k0 + seg;
                uint32_t so = (uint32_t)(row * LDS + seg);
                cpa16(cvta_s(base + 2 * A_HALVES + so), Wh + wo);
                cpa16(cvta_s(base + 2 * A_HALVES + B_HALVES + so), Wl + wo);
            }
        }
        asm volatile("cp.async.commit_group;\n");
    };

    loadStage(0, 0);

    for (int kt = 0; kt < NK; ++kt) {
        int st = kt & 1;
        if (kt + 1 < NK) {
            loadStage(kt + 1, st ^ 1);
            asm volatile("cp.async.wait_group 1;\n" ::: "memory");
        } else {
            asm volatile("cp.async.wait_group 0;\n" ::: "memory");
        }
        __syncthreads();

        __nv_bfloat16* base = dsm + st * STAGE_HALVES;
        __nv_bfloat16* sAh = base;
        __nv_bfloat16* sAl = base + A_HALVES;
        __nv_bfloat16* sBh = base + 2 * A_HALVES;
        __nv_bfloat16* sBl = base + 2 * A_HALVES + B_HALVES;

#pragma unroll
        for (int ks = 0; ks < 2; ks++) {
            int kc = ks * 16;
            uint32_t ah[2][4], al[2][4];
#pragma unroll
            for (int i = 0; i < 2; i++) {
                int r = wm + i * 16 + (lane & 15);
                int c = kc + ((lane >> 4) & 1) * 8;
                ldm_x4(ah[i][0], ah[i][1], ah[i][2], ah[i][3], cvta_s(sAh + r * LDS + c));
                ldm_x4(al[i][0], al[i][1], al[i][2], al[i][3], cvta_s(sAl + r * LDS + c));
            }
#pragma unroll
            for (int jj = 0; jj < 4; jj++) {
                int r = wn + jj * 16 + (lane & 7) + ((lane >> 4) & 1) * 8;
                int c = kc + ((lane >> 3) & 1) * 8;
                uint32_t bh[4], bl[4];
                ldm_x4(bh[0], bh[1], bh[2], bh[3], cvta_s(sBh + r * LDS + c));
                ldm_x4(bl[0], bl[1], bl[2], bl[3], cvta_s(sBl + r * LDS + c));
#pragma unroll
                for (int i = 0; i < 2; i++) {
                    float* a0 = acc[i][jj * 2 + 0];
                    float* a1 = acc[i][jj * 2 + 1];
                    mma_bf16(a0, ah[i][0], ah[i][1], ah[i][2], ah[i][3], bh[0], bh[1]);
                    mma_bf16(a0, ah[i][0], ah[i][1], ah[i][2], ah[i][3], bl[0], bl[1]);
                    mma_bf16(a0, al[i][0], al[i][1], al[i][2], al[i][3], bh[0], bh[1]);
                    mma_bf16(a1, ah[i][0], ah[i][1], ah[i][2], ah[i][3], bh[2], bh[3]);
                    mma_bf16(a1, ah[i][0], ah[i][1], ah[i][2], ah[i][3], bl[2], bl[3]);
                    mma_bf16(a1, al[i][0], al[i][1], al[i][2], al[i][3], bh[2], bh[3]);
                }
            }
        }
        __syncthreads();
    }

    // epilogue: bias + relu + pad-zero + store fp32 + bf16 split + fused BN stats
#pragma unroll
    for (int j = 0; j < 8; j++) {
        int c = n0 + wn + j * 8 + (lane & 3) * 2;
        float bx = 0.f, by = 0.f;
        if (bias) { float2 bb = *(const float2*)(bias + c); bx = bb.x; by = bb.y; }
        float s0 = 0.f, s1 = 0.f, q0 = 0.f, q1 = 0.f;
#pragma unroll
        for (int i = 0; i < 2; i++) {
            int r = m0 + wm + i * 16 + (lane >> 2);
            bool va = r < NN, vb = (r + 8) < NN;
            float v00 = va ? fmaxf(acc[i][j][0] + bx, 0.f) : 0.f;
            float v01 = va ? fmaxf(acc[i][j][1] + by, 0.f) : 0.f;
            float v10 = vb ? fmaxf(acc[i][j][2] + bx, 0.f) : 0.f;
            float v11 = vb ? fmaxf(acc[i][j][3] + by, 0.f) : 0.f;
            *(float2*)(C + (size_t)r * HH + c) = make_float2(v00, v01);
            *(float2*)(C + (size_t)(r + 8) * HH + c) = make_float2(v10, v11);
            if (oh) {
                __nv_bfloat16 h00 = __float2bfloat16(v00), h01 = __float2bfloat16(v01);
                __nv_bfloat16 h10 = __float2bfloat16(v10), h11 = __float2bfloat16(v11);
                *(__nv_bfloat162*)(oh + (size_t)r * HH + c) = __nv_bfloat162(h00, h01);
                *(__nv_bfloat162*)(oh + (size_t)(r + 8) * HH + c) = __nv_bfloat162(h10, h11);
                *(__nv_bfloat162*)(ol + (size_t)r * HH + c) = __nv_bfloat162(
                    __float2bfloat16(v00 - __bfloat162float(h00)),
                    __float2bfloat16(v01 - __bfloat162float(h01)));
                *(__nv_bfloat162*)(ol + (size_t)(r + 8) * HH + c) = __nv_bfloat162(
                    __float2bfloat16(v10 - __bfloat162float(h10)),
                    __float2bfloat16(v11 - __bfloat162float(h11)));
            }
            s0 += v00 + v10; s1 += v01 + v11;
            q0 += v00 * v00 + v10 * v10; q1 += v01 * v01 + v11 * v11;
        }
#pragma unroll
        for (int o = 16; o >= 4; o >>= 1) {
            s0 += __shfl_down_sync(0xffffffff, s0, o);
            s1 += __shfl_down_sync(0xffffffff, s1, o);
            q0 += __shfl_down_sync(0xffffffff, q0, o);
            q1 += __shfl_down_sync(0xffffffff, q1, o);
        }
        if (lane < 4) {
            int cc = n0 + wn + j * 8 + lane * 2;
            atomicAdd(&g_sum[cc], s0);
            atomicAdd(&g_sum[cc + 1], s1);
            atomicAdd(&g_sq[cc], q0);
            atomicAdd(&g_sq[cc + 1], q1);
        }
    }
}

// ---------------- final conv (C=10) + log_softmax ----------------
__global__ __launch_bounds__(320)
void k_final(const float* __restrict__ agg, const float* __restrict__ r,
             const float* __restrict__ Wr, const float* __restrict__ Ww,
             float* __restrict__ out) {
    __shared__ float sa[HH];
    __shared__ float sh[HH];
    __shared__ float slog[CC];
    __shared__ float sLse;
    int node = blockIdx.x;
    int t = threadIdx.x;
    for (int i = t; i < HH; i += 320) {
        sa[i] = agg[(size_t)node * HH + i];
        sh[i] = r[(size_t)node * HH + i] * g_bnA[i] + g_bnB[i];
    }
    __syncthreads();
    int w = t >> 5, lane = t & 31;
    float s = 0.f;
    for (int k = lane; k < HH; k += 32)
        s += sa[k] * Wr[w * HH + k] + sh[k] * Ww[w * HH + k];
#pragma unroll
    for (int o = 16; o; o >>= 1) s += __shfl_down_sync(0xffffffff, s, o);
    if (lane == 0) slog[w] = s;
    __syncthreads();
    if (t == 0) {
        float mx = slog[0];
        for (int c = 1; c < CC; c++) mx = fmaxf(mx, slog[c]);
        float sum = 0.f;
        for (int c = 0; c < CC; c++) sum += expf(slog[c] - mx);
        sLse = mx + logf(sum);
    }
    __syncthreads();
    if (t < CC) out[(size_t)node * CC + t] = slog[t] - sLse;
}

// ---------------- launch ----------------
extern "C" void kernel_launch(void* const* d_in, const int* in_sizes, int n_in,
                              void* d_out, int out_size) {
    const float* x     = (const float*)d_in[0];
    const int*   ei    = (const int*)d_in[1];
    const float* Wpr   = (const float*)d_in[2];
    const float* Wpw   = (const float*)d_in[3];
    const float* Wrel  = (const float*)d_in[4];
    const float* Wroot = (const float*)d_in[5];
    const float* gamma = (const float*)d_in[6];
    const float* beta  = (const float*)d_in[7];
    const float* Wfr   = (const float*)d_in[8];
    const float* Wfw   = (const float*)d_in[9];
    float* out = (float*)d_out;

    static float *p_h1 = nullptr, *p_h2 = nullptr, *p_agg = nullptr, *p_bias = nullptr;
    static __nv_bfloat16 *p_xh, *p_xl, *p_hh1, *p_hl1, *p_hh2, *p_hl2,
                         *p_ah, *p_al, *p_wh, *p_wl, *p_fwh, *p_fwl;
    if (!p_h1) {
        cudaGetSymbolAddress((void**)&p_h1, g_h1);
        cudaGetSymbolAddress((void**)&p_h2, g_h2);
        cudaGetSymbolAddress((void**)&p_agg, g_agg);
        cudaGetSymbolAddress((void**)&p_bias, g_bias);
        cudaGetSymbolAddress((void**)&p_xh, g_xh);
        cudaGetSymbolAddress((void**)&p_xl, g_xl);
        cudaGetSymbolAddress((void**)&p_hh1, g_hh1);
        cudaGetSymbolAddress((void**)&p_hl1, g_hl1);
        cudaGetSymbolAddress((void**)&p_hh2, g_hh2);
        cudaGetSymbolAddress((void**)&p_hl2, g_hl2);
        cudaGetSymbolAddress((void**)&p_ah, g_ah);
        cudaGetSymbolAddress((void**)&p_al, g_al);
        cudaGetSymbolAddress((void**)&p_wh, g_wh);
        cudaGetSymbolAddress((void**)&p_wl, g_wl);
        cudaGetSymbolAddress((void**)&p_fwh, g_fwh);
        cudaGetSymbolAddress((void**)&p_fwl, g_fwl);
        cudaFuncSetAttribute(k_gemm6, cudaFuncAttributeMaxDynamicSharedMemorySize, GEMM_SMEM);
    }

    dim3 gemmGrid(HH / 128, NP / 96);   // (4, 106) = 424 CTAs
    int eb = (EE + 255) / 256;
    int prepb = (PREP_TOTAL + 255) / 256;

    // CSR
    k_deg<<<eb, 256>>>(ei);
    k_scanscale<<<1, 1024>>>();
    k_fill<<<eb, 256>>>(ei);
    k_agg2<<<NN, 128>>>(x, 0, p_ah, p_al, nullptr);
    k_prep<<<prepb, 256>>>(x, Wpr, Wpw);

    // proj layer: raw z1 = relu(conv(x)); epilogue emits z1 fp32 + splits + stats
    k_gemm6<<<gemmGrid, 192, GEMM_SMEM>>>(p_ah, p_al, p_xh, p_xl,
                                          p_wh, p_wl, p_wh + MM, p_wl + MM,
                                          nullptr, p_h1, p_hh1, p_hl1);
    k_bnfin<<<1, HH>>>(gamma, beta);

    float* cur = p_h1;
    float* nxt = p_h2;
    __nv_bfloat16 *chh = p_hh1, *chl = p_hl1;    // splits of cur
    __nv_bfloat16 *nhh = p_hh2, *nhl = p_hl2;
    for (int l = 0; l < 3; ++l) {
        // fold BN of cur into this layer's weights (+ bias)
        k_fold<<<2050, 256>>>(Wrel + (size_t)l * MM, Wroot + (size_t)l * MM);
        // mean-aggregate raw z (BN folded into weights)
        k_agg2<<<NN, 128>>>(cur, 0, p_ah, p_al, nullptr);
        bool last = (l == 2);
        k_gemm6<<<gemmGrid, 192, GEMM_SMEM>>>(p_ah, p_al, chh, chl,
                                              p_fwh, p_fwl, p_fwh + MM, p_fwl + MM,
                                              p_bias, nxt,
                                              last ? nullptr : nhh, last ? nullptr : nhl);
        k_bnfin<<<1, HH>>>(gamma + (size_t)(l + 1) * HH, beta + (size_t)(l + 1) * HH);
        float* tf = cur; cur = nxt; nxt = tf;
        __nv_bfloat16* t1 = chh; chh = nhh; nhh = t1;
        __nv_bfloat16* t2 = chl; chl = nhl; nhl = t2;
    }

    // final conv + log_softmax (explicit BN: agg side in k_agg2, root side in k_final)
    k_agg2<<<NN, 128>>>(cur, 1, nullptr, nullptr, p_agg);
    k_final<<<NN, 320>>>(p_agg, cur, Wfr, Wfw, out);
}

// round 10
// speedup vs baseline: 1.5461x; 1.5461x over previous
#include <cuda_runtime.h>
#include <cuda_bf16.h>
#include <math.h>
#include <stdint.h>

#define NN 10000
#define NP 10176            // 106 * 96
#define EE 160000
#define HH 512
#define CC 10
#define MM (HH * HH)
#define BN_EPS 1e-5f

// ---------------- device scratch ----------------
__device__ float g_h1[NP * HH];      // raw relu(conv) output (pre-BN)
__device__ float g_h2[NP * HH];
__device__ float g_agg[NP * HH];
__device__ __nv_bfloat16 g_xh[NP * HH], g_xl[NP * HH];
__device__ __nv_bfloat16 g_hh[NP * HH], g_hl[NP * HH];
__device__ __nv_bfloat16 g_ah[NP * HH], g_al[NP * HH];
__device__ __nv_bfloat16 g_wh[8 * MM], g_wl[8 * MM];
__device__ float g_scale[NN];
__device__ int   g_degi[NN];         // zeroed per-node inside k_agg2
__device__ int   g_rowptr[NN + 1];
__device__ int   g_fill[NN];
__device__ int   g_esrc[EE];
__device__ float g_sum[HH];
__device__ float g_sq[HH];
__device__ float g_bnA[HH];
__device__ float g_bnB[HH];

// ---------------- PTX helpers ----------------
__device__ __forceinline__ uint32_t cvta_s(const void* p) {
    return (uint32_t)__cvta_generic_to_shared(p);
}
__device__ __forceinline__ void cpa16(uint32_t dst, const void* src) {
    asm volatile("cp.async.cg.shared.global [%0], [%1], 16;\n" :: "r"(dst), "l"(src));
}
__device__ __forceinline__ void ldm_x4(uint32_t& r0, uint32_t& r1, uint32_t& r2, uint32_t& r3, uint32_t addr) {
    asm volatile("ldmatrix.sync.aligned.m8n8.x4.shared.b16 {%0,%1,%2,%3}, [%4];\n"
                 : "=r"(r0), "=r"(r1), "=r"(r2), "=r"(r3) : "r"(addr));
}
__device__ __forceinline__ void mma_bf16(float* d, uint32_t a0, uint32_t a1, uint32_t a2, uint32_t a3,
                                         uint32_t b0, uint32_t b1) {
    asm volatile("mma.sync.aligned.m16n8k16.row.col.f32.bf16.bf16.f32 "
                 "{%0,%1,%2,%3}, {%4,%5,%6,%7}, {%8,%9}, {%0,%1,%2,%3};\n"
                 : "+f"(d[0]), "+f"(d[1]), "+f"(d[2]), "+f"(d[3])
                 : "r"(a0), "r"(a1), "r"(a2), "r"(a3), "r"(b0), "r"(b1));
}

// ---------------- fused prep: pads, x + all weight splits, stats zero ----------------
#define SPLITX (NN * HH)
#define SPLITW (8 * MM)
#define PADSZ  ((NP - NN) * HH)
#define PREP_TOTAL (SPLITX + SPLITW + PADSZ + HH)

__global__ void k_prep(const float* __restrict__ x,
                       const float* __restrict__ Wpr, const float* __restrict__ Wpw,
                       const float* __restrict__ Wrel, const float* __restrict__ Wroot) {
    int i = blockIdx.x * blockDim.x + threadIdx.x;
    if (i < SPLITX) {
        float v = x[i];
        __nv_bfloat16 h = __float2bfloat16(v);
        g_xh[i] = h;
        g_xl[i] = __float2bfloat16(v - __bfloat162float(h));
        return;
    }
    i -= SPLITX;
    if (i < SPLITW) {
        int w = i >> 18;
        int off = i & (MM - 1);
        const float* src;
        if (w == 0) src = Wpr + off;
        else if (w == 1) src = Wpw + off;
        else if (w < 5) src = Wrel + (size_t)(w - 2) * MM + off;
        else src = Wroot + (size_t)(w - 5) * MM + off;
        float v = *src;
        __nv_bfloat16 h = __float2bfloat16(v);
        g_wh[i] = h;
        g_wl[i] = __float2bfloat16(v - __bfloat162float(h));
        return;
    }
    i -= SPLITW;
    if (i < PADSZ) {
        int off = NN * HH + i;
        __nv_bfloat16 z = __float2bfloat16(0.0f);
        g_xh[off] = z; g_xl[off] = z;
        g_hh[off] = z; g_hl[off] = z;
        g_ah[off] = z; g_al[off] = z;
        return;
    }
    i -= PADSZ;
    if (i < HH) { g_sum[i] = 0.f; g_sq[i] = 0.f; }
}

// ---------------- CSR build ----------------
__global__ void k_deg(const int* __restrict__ ei) {
    int e = blockIdx.x * blockDim.x + threadIdx.x;
    if (e < EE) atomicAdd(&g_degi[ei[EE + e]], 1);
}
__global__ void k_scanscale() {
    __shared__ int warp_part[32];
    __shared__ int carry;
    int t = threadIdx.x;
    int lane = t & 31, w = t >> 5;
    if (t == 0) carry = 0;
    __syncthreads();
    for (int base = 0; base < NN; base += 1024) {
        int i = base + t;
        int v = (i < NN) ? g_degi[i] : 0;
        if (i < NN) g_scale[i] = 1.0f / (float)(v > 0 ? v : 1);
        int s = v;
#pragma unroll
        for (int o = 1; o < 32; o <<= 1) {
            int u = __shfl_up_sync(0xffffffff, s, o);
            if (lane >= o) s += u;
        }
        if (lane == 31) warp_part[w] = s;
        __syncthreads();
        if (w == 0) {
            int p = warp_part[lane];
#pragma unroll
            for (int o = 1; o < 32; o <<= 1) {
                int u = __shfl_up_sync(0xffffffff, p, o);
                if (lane >= o) p += u;
            }
            warp_part[lane] = p;
        }
        __syncthreads();
        int add = (w > 0) ? warp_part[w - 1] : 0;
        int inc = s + add + carry;
        if (i < NN) g_rowptr[i + 1] = inc;
        __syncthreads();
        if (t == 1023) carry = inc;
        __syncthreads();
    }
    if (t == 0) g_rowptr[0] = 0;
}
__global__ void k_fill(const int* __restrict__ ei) {
    int e = blockIdx.x * blockDim.x + threadIdx.x;
    if (e < EE) {
        int dst = ei[EE + e];
        int pos = g_rowptr[dst] + atomicAdd(&g_fill[dst], 1);
        g_esrc[pos] = ei[e];
    }
}

// ---------------- mean aggregation + optional BN affine + bf16 split ----------------
__global__ void k_agg2(const float* __restrict__ h, int useBN,
                       __nv_bfloat16* __restrict__ oh, __nv_bfloat16* __restrict__ ol,
                       float* __restrict__ of) {
    int node = blockIdx.x;
    int t = threadIdx.x;
    if (t == 0) { g_degi[node] = 0; g_fill[node] = 0; }   // reset for next replay
    int s = g_rowptr[node];
    int e = g_rowptr[node + 1];
    float ax = 0.f, ay = 0.f, az = 0.f, aw = 0.f;
    int j = s;
    for (; j + 1 < e; j += 2) {
        int s0 = g_esrc[j];
        int s1 = g_esrc[j + 1];
        float4 v0 = ((const float4*)(h + (size_t)s0 * HH))[t];
        float4 v1 = ((const float4*)(h + (size_t)s1 * HH))[t];
        ax += v0.x + v1.x; ay += v0.y + v1.y;
        az += v0.z + v1.z; aw += v0.w + v1.w;
    }
    if (j < e) {
        int s0 = g_esrc[j];
        float4 v0 = ((const float4*)(h + (size_t)s0 * HH))[t];
        ax += v0.x; ay += v0.y; az += v0.z; aw += v0.w;
    }
    float sc = g_scale[node];
    ax *= sc; ay *= sc; az *= sc; aw *= sc;
    if (useBN) {
        float4 a = ((const float4*)g_bnA)[t];
        float4 b = ((const float4*)g_bnB)[t];
        ax = ax * a.x + b.x; ay = ay * a.y + b.y;
        az = az * a.z + b.z; aw = aw * a.w + b.w;
    }
    if (of) {
        ((float4*)(of + (size_t)node * HH))[t] = make_float4(ax, ay, az, aw);
    }
    if (oh) {
        __nv_bfloat16 hx = __float2bfloat16(ax), hy = __float2bfloat16(ay);
        __nv_bfloat16 hz = __float2bfloat16(az), hw = __float2bfloat16(aw);
        __nv_bfloat16 lx = __float2bfloat16(ax - __bfloat162float(hx));
        __nv_bfloat16 ly = __float2bfloat16(ay - __bfloat162float(hy));
        __nv_bfloat16 lz = __float2bfloat16(az - __bfloat162float(hz));
        __nv_bfloat16 lw = __float2bfloat16(aw - __bfloat162float(hw));
        __nv_bfloat162* ph = (__nv_bfloat162*)(oh + (size_t)node * HH);
        __nv_bfloat162* pl = (__nv_bfloat162*)(ol + (size_t)node * HH);
        ph[t * 2 + 0] = __nv_bfloat162(hx, hy);
        ph[t * 2 + 1] = __nv_bfloat162(hz, hw);
        pl[t * 2 + 0] = __nv_bfloat162(lx, ly);
        pl[t * 2 + 1] = __nv_bfloat162(lz, lw);
    }
}

// ---------------- mma.sync dual GEMM, 96x128 tile, BK=32 ----------------
// nk=32: dual (A1@W1^T over k<16 chunks, A2@W2^T over k>=16). nk=16: single pair.
// finalize=0: store raw fp32 acc (partial). finalize=1: acc += Cin (if given),
// relu, store, fused BN stats.
#define LDS 40
#define A_HALVES (96 * LDS)
#define B_HALVES (128 * LDS)
#define STAGE_HALVES (2 * A_HALVES + 2 * B_HALVES)
#define GEMM_SMEM (2 * STAGE_HALVES * 2)

__global__ __launch_bounds__(192, 3)
void k_gemm6(const __nv_bfloat16* __restrict__ a1h, const __nv_bfloat16* __restrict__ a1l,
             const __nv_bfloat16* __restrict__ a2h, const __nv_bfloat16* __restrict__ a2l,
             const __nv_bfloat16* __restrict__ w1h, const __nv_bfloat16* __restrict__ w1l,
             const __nv_bfloat16* __restrict__ w2h, const __nv_bfloat16* __restrict__ w2l,
             float* __restrict__ C, const float* __restrict__ Cin,
             int nk, int finalize) {
    extern __shared__ __nv_bfloat16 dsm[];

    const int tx = threadIdx.x;
    const int lane = tx & 31;
    const int warp = tx >> 5;
    const int wm = (warp % 3) * 32;
    const int wn = (warp / 3) * 64;
    const int m0 = blockIdx.y * 96;
    const int n0 = blockIdx.x * 128;

    float acc[2][8][4];
#pragma unroll
    for (int i = 0; i < 2; i++)
#pragma unroll
        for (int j = 0; j < 8; j++)
#pragma unroll
            for (int q = 0; q < 4; q++) acc[i][j][q] = 0.f;

    auto loadStage = [&](int kt, int st) {
        const __nv_bfloat16* Ah = (kt < 16) ? a1h : a2h;
        const __nv_bfloat16* Al = (kt < 16) ? a1l : a2l;
        const __nv_bfloat16* Wh = (kt < 16) ? w1h : w2h;
        const __nv_bfloat16* Wl = (kt < 16) ? w1l : w2l;
        int k0 = (kt & 15) * 32;
        __nv_bfloat16* base = dsm + st * STAGE_HALVES;
#pragma unroll
        for (int rep = 0; rep < 2; rep++) {
            int idx = tx + rep * 192;
            int row = idx >> 2;
            int seg = (idx & 3) * 8;
            size_t ao = (size_t)(m0 + row) * HH + k0 + seg;
            uint32_t so = (uint32_t)(row * LDS + seg);
            cpa16(cvta_s(base + so), Ah + ao);
            cpa16(cvta_s(base + A_HALVES + so), Al + ao);
        }
#pragma unroll
        for (int rep = 0; rep < 3; rep++) {
            int idx = tx + rep * 192;
            if (idx < 512) {
                int row = idx >> 2;
                int seg = (idx & 3) * 8;
                size_t wo = (size_t)(n0 + row) * HH + k0 + seg;
                uint32_t so = (uint32_t)(row * LDS + seg);
                cpa16(cvta_s(base + 2 * A_HALVES + so), Wh + wo);
                cpa16(cvta_s(base + 2 * A_HALVES + B_HALVES + so), Wl + wo);
            }
        }
        asm volatile("cp.async.commit_group;\n");
    };

    loadStage(0, 0);

    for (int kt = 0; kt < nk; ++kt) {
        int st = kt & 1;
        if (kt + 1 < nk) {
            loadStage(kt + 1, st ^ 1);
            asm volatile("cp.async.wait_group 1;\n" ::: "memory");
        } else {
            asm volatile("cp.async.wait_group 0;\n" ::: "memory");
        }
        __syncthreads();

        __nv_bfloat16* base = dsm + st * STAGE_HALVES;
        __nv_bfloat16* sAh = base;
        __nv_bfloat16* sAl = base + A_HALVES;
        __nv_bfloat16* sBh = base + 2 * A_HALVES;
        __nv_bfloat16* sBl = base + 2 * A_HALVES + B_HALVES;

#pragma unroll
        for (int ks = 0; ks < 2; ks++) {
            int kc = ks * 16;
            uint32_t ah[2][4], al[2][4];
#pragma unroll
            for (int i = 0; i < 2; i++) {
                int r = wm + i * 16 + (lane & 15);
                int c = kc + ((lane >> 4) & 1) * 8;
                ldm_x4(ah[i][0], ah[i][1], ah[i][2], ah[i][3], cvta_s(sAh + r * LDS + c));
                ldm_x4(al[i][0], al[i][1], al[i][2], al[i][3], cvta_s(sAl + r * LDS + c));
            }
#pragma unroll
            for (int jj = 0; jj < 4; jj++) {
                int r = wn + jj * 16 + (lane & 7) + ((lane >> 4) & 1) * 8;
                int c = kc + ((lane >> 3) & 1) * 8;
                uint32_t bh[4], bl[4];
                ldm_x4(bh[0], bh[1], bh[2], bh[3], cvta_s(sBh + r * LDS + c));
                ldm_x4(bl[0], bl[1], bl[2], bl[3], cvta_s(sBl + r * LDS + c));
#pragma unroll
                for (int i = 0; i < 2; i++) {
                    float* a0 = acc[i][jj * 2 + 0];
                    float* a1 = acc[i][jj * 2 + 1];
                    mma_bf16(a0, ah[i][0], ah[i][1], ah[i][2], ah[i][3], bh[0], bh[1]);
                    mma_bf16(a0, ah[i][0], ah[i][1], ah[i][2], ah[i][3], bl[0], bl[1]);
                    mma_bf16(a0, al[i][0], al[i][1], al[i][2], al[i][3], bh[0], bh[1]);
                    mma_bf16(a1, ah[i][0], ah[i][1], ah[i][2], ah[i][3], bh[2], bh[3]);
                    mma_bf16(a1, ah[i][0], ah[i][1], ah[i][2], ah[i][3], bl[2], bl[3]);
                    mma_bf16(a1, al[i][0], al[i][1], al[i][2], al[i][3], bh[2], bh[3]);
                }
            }
        }
        __syncthreads();
    }

    if (!finalize) {
        // store raw partial acc
#pragma unroll
        for (int j = 0; j < 8; j++) {
#pragma unroll
            for (int i = 0; i < 2; i++) {
                int r = m0 + wm + i * 16 + (lane >> 2);
                int c = n0 + wn + j * 8 + (lane & 3) * 2;
                *(float2*)(C + (size_t)r * HH + c) = make_float2(acc[i][j][0], acc[i][j][1]);
                *(float2*)(C + (size_t)(r + 8) * HH + c) = make_float2(acc[i][j][2], acc[i][j][3]);
            }
        }
        return;
    }

    // finalize: (+Cin) + relu + store + fused BN column stats
#pragma unroll
    for (int j = 0; j < 8; j++) {
        float s0 = 0.f, s1 = 0.f, q0 = 0.f, q1 = 0.f;
#pragma unroll
        for (int i = 0; i < 2; i++) {
            int r = m0 + wm + i * 16 + (lane >> 2);
            int c = n0 + wn + j * 8 + (lane & 3) * 2;
            float v00 = acc[i][j][0], v01 = acc[i][j][1];
            float v10 = acc[i][j][2], v11 = acc[i][j][3];
            if (Cin) {
                float2 p0 = *(const float2*)(Cin + (size_t)r * HH + c);
                float2 p1 = *(const float2*)(Cin + (size_t)(r + 8) * HH + c);
                v00 += p0.x; v01 += p0.y; v10 += p1.x; v11 += p1.y;
            }
            v00 = fmaxf(v00, 0.f); v01 = fmaxf(v01, 0.f);
            v10 = fmaxf(v10, 0.f); v11 = fmaxf(v11, 0.f);
            *(float2*)(C + (size_t)r * HH + c) = make_float2(v00, v01);
            *(float2*)(C + (size_t)(r + 8) * HH + c) = make_float2(v10, v11);
            s0 += v00 + v10; s1 += v01 + v11;
            q0 += v00 * v00 + v10 * v10; q1 += v01 * v01 + v11 * v11;
        }
#pragma unroll
        for (int o = 16; o >= 4; o >>= 1) {
            s0 += __shfl_down_sync(0xffffffff, s0, o);
            s1 += __shfl_down_sync(0xffffffff, s1, o);
            q0 += __shfl_down_sync(0xffffffff, q0, o);
            q1 += __shfl_down_sync(0xffffffff, q1, o);
        }
        if (lane < 4) {
            int cc = n0 + wn + j * 8 + lane * 2;
            atomicAdd(&g_sum[cc], s0);
            atomicAdd(&g_sum[cc + 1], s1);
            atomicAdd(&g_sq[cc], q0);
            atomicAdd(&g_sq[cc + 1], q1);
        }
    }
}

// ---------------- BatchNorm finalize (reads + self-zeroes stats) ----------------
__global__ void k_bnfin(const float* __restrict__ gamma, const float* __restrict__ beta) {
    int f = threadIdx.x;
    float s = g_sum[f];
    float q = g_sq[f];
    g_sum[f] = 0.f;
    g_sq[f] = 0.f;
    float mu = s / (float)NN;
    float var = q / (float)NN - mu * mu;
    float inv = rsqrtf(var + BN_EPS);
    float sc = gamma[f] * inv;
    g_bnA[f] = sc;
    g_bnB[f] = beta[f] - mu * sc;
}
// BN apply + bf16 hi/lo split (root operand only)
__global__ void k_bnapply2(const float* __restrict__ h,
                           __nv_bfloat16* __restrict__ hh, __nv_bfloat16* __restrict__ hl) {
    int idx = blockIdx.x * blockDim.x + threadIdx.x;
    if (idx >= NN * HH / 4) return;
    int f4 = idx & (HH / 4 - 1);
    float4 v = ((const float4*)h)[idx];
    float4 a = ((const float4*)g_bnA)[f4];
    float4 b = ((const float4*)g_bnB)[f4];
    v.x = v.x * a.x + b.x;
    v.y = v.y * a.y + b.y;
    v.z = v.z * a.z + b.z;
    v.w = v.w * a.w + b.w;
    __nv_bfloat16 hx = __float2bfloat16(v.x), hy = __float2bfloat16(v.y);
    __nv_bfloat16 hz = __float2bfloat16(v.z), hw = __float2bfloat16(v.w);
    __nv_bfloat16 lx = __float2bfloat16(v.x - __bfloat162float(hx));
    __nv_bfloat16 ly = __float2bfloat16(v.y - __bfloat162float(hy));
    __nv_bfloat16 lz = __float2bfloat16(v.z - __bfloat162float(hz));
    __nv_bfloat16 lw = __float2bfloat16(v.w - __bfloat162float(hw));
    ((__nv_bfloat162*)hh)[idx * 2 + 0] = __nv_bfloat162(hx, hy);
    ((__nv_bfloat162*)hh)[idx * 2 + 1] = __nv_bfloat162(hz, hw);
    ((__nv_bfloat162*)hl)[idx * 2 + 0] = __nv_bfloat162(lx, ly);
    ((__nv_bfloat162*)hl)[idx * 2 + 1] = __nv_bfloat162(lz, lw);
}

// ---------------- final conv (C=10) + log_softmax ----------------
__global__ __launch_bounds__(320)
void k_final(const float* __restrict__ agg, const float* __restrict__ r,
             const float* __restrict__ Wr, const float* __restrict__ Ww,
             float* __restrict__ out) {
    __shared__ float sa[HH];
    __shared__ float sh[HH];
    __shared__ float slog[CC];
    __shared__ float sLse;
    int node = blockIdx.x;
    int t = threadIdx.x;
    for (int i = t; i < HH; i += 320) {
        sa[i] = agg[(size_t)node * HH + i];
        sh[i] = r[(size_t)node * HH + i] * g_bnA[i] + g_bnB[i];
    }
    __syncthreads();
    int w = t >> 5, lane = t & 31;
    float s = 0.f;
    for (int k = lane; k < HH; k += 32)
        s += sa[k] * Wr[w * HH + k] + sh[k] * Ww[w * HH + k];
#pragma unroll
    for (int o = 16; o; o >>= 1) s += __shfl_down_sync(0xffffffff, s, o);
    if (lane == 0) slog[w] = s;
    __syncthreads();
    if (t == 0) {
        float mx = slog[0];
        for (int c = 1; c < CC; c++) mx = fmaxf(mx, slog[c]);
        float sum = 0.f;
        for (int c = 0; c < CC; c++) sum += expf(slog[c] - mx);
        sLse = mx + logf(sum);
    }
    __syncthreads();
    if (t < CC) out[(size_t)node * CC + t] = slog[t] - sLse;
}

// ---------------- launch ----------------
extern "C" void kernel_launch(void* const* d_in, const int* in_sizes, int n_in,
                              void* d_out, int out_size) {
    const float* x     = (const float*)d_in[0];
    const int*   ei    = (const int*)d_in[1];
    const float* Wpr   = (const float*)d_in[2];
    const float* Wpw   = (const float*)d_in[3];
    const float* Wrel  = (const float*)d_in[4];
    const float* Wroot = (const float*)d_in[5];
    const float* gamma = (const float*)d_in[6];
    const float* beta  = (const float*)d_in[7];
    const float* Wfr   = (const float*)d_in[8];
    const float* Wfw   = (const float*)d_in[9];
    float* out = (float*)d_out;

    static float *p_h1 = nullptr, *p_h2 = nullptr, *p_agg = nullptr;
    static __nv_bfloat16 *p_xh, *p_xl, *p_hh, *p_hl, *p_ah, *p_al, *p_wh, *p_wl;
    if (!p_h1) {
        cudaGetSymbolAddress((void**)&p_h1, g_h1);
        cudaGetSymbolAddress((void**)&p_h2, g_h2);
        cudaGetSymbolAddress((void**)&p_agg, g_agg);
        cudaGetSymbolAddress((void**)&p_xh, g_xh);
        cudaGetSymbolAddress((void**)&p_xl, g_xl);
        cudaGetSymbolAddress((void**)&p_hh, g_hh);
        cudaGetSymbolAddress((void**)&p_hl, g_hl);
        cudaGetSymbolAddress((void**)&p_ah, g_ah);
        cudaGetSymbolAddress((void**)&p_al, g_al);
        cudaGetSymbolAddress((void**)&p_wh, g_wh);
        cudaGetSymbolAddress((void**)&p_wl, g_wl);
        cudaFuncSetAttribute(k_gemm6, cudaFuncAttributeMaxDynamicSharedMemorySize, GEMM_SMEM);
    }

    dim3 gemmGrid(HH / 128, NP / 96);   // (4, 106) = 424 CTAs
    int eb = (EE + 255) / 256;
    int apb = (NN * HH / 4 + 255) / 256;
    int prepb = (PREP_TOTAL + 255) / 256;

    // 1: deg, 2: prep, 3: scan+scale, 4: GEMM(root half of proj) <- profiled window
    k_deg<<<eb, 256>>>(ei);
    k_prep<<<prepb, 256>>>(x, Wpr, Wpw, Wrel, Wroot);
    k_scanscale<<<1, 1024>>>();
    k_gemm6<<<gemmGrid, 192, GEMM_SMEM>>>(p_xh, p_xl, p_xh, p_xl,
                                          p_wh + 1 * MM, p_wl + 1 * MM,
                                          p_wh + 1 * MM, p_wl + 1 * MM,
                                          p_h1, nullptr, 16, 0);   // raw x@Wpw^T
    // 5: fill, 6: agg(x), 7: GEMM(rel half, finalize: +agg@Wpr^T, relu, stats)
    k_fill<<<eb, 256>>>(ei);
    k_agg2<<<NN, 128>>>(x, 0, p_ah, p_al, nullptr);
    k_gemm6<<<gemmGrid, 192, GEMM_SMEM>>>(p_ah, p_al, p_ah, p_al,
                                          p_wh + 0 * MM, p_wl + 0 * MM,
                                          p_wh + 0 * MM, p_wl + 0 * MM,
                                          p_h1, p_h1, 16, 1);
    k_bnfin<<<1, HH>>>(gamma, beta);
    k_bnapply2<<<apb, 256>>>(p_h1, p_hh, p_hl);

    float* cur = p_h1;
    float* nxt = p_h2;
    for (int l = 0; l < 3; ++l) {
        k_agg2<<<NN, 128>>>(cur, 1, p_ah, p_al, nullptr);
        k_gemm6<<<gemmGrid, 192, GEMM_SMEM>>>(p_ah, p_al, p_hh, p_hl,
                                              p_wh + (2 + l) * MM, p_wl + (2 + l) * MM,
                                              p_wh + (5 + l) * MM, p_wl + (5 + l) * MM,
                                              nxt, nullptr, 32, 1);
        k_bnfin<<<1, HH>>>(gamma + (size_t)(l + 1) * HH, beta + (size_t)(l + 1) * HH);
        if (l < 2)
            k_bnapply2<<<apb, 256>>>(nxt, p_hh, p_hl);
        float* tmp = cur; cur = nxt; nxt = tmp;
    }

    k_agg2<<<NN, 128>>>(cur, 1, nullptr, nullptr, p_agg);
    k_final<<<NN, 320>>>(p_agg, cur, Wfr, Wfw, out);
}

// round 11
// speedup vs baseline: 2.0330x; 1.3150x over previous
#include <cuda_runtime.h>
#include <cuda_fp16.h>
#include <math.h>
#include <stdint.h>

#define NN 10000
#define NP 10176            // 106 * 96
#define EE 160000
#define HH 512
#define CC 10
#define MM (HH * HH)
#define BN_EPS 1e-5f

// ---------------- device scratch ----------------
__device__ float g_h1[NP * HH];      // raw relu(conv) output (pre-BN)
__device__ float g_h2[NP * HH];
__device__ float g_agg[NP * HH];
__device__ __half g_xh[NP * HH], g_xl[NP * HH];   // x fp16 hi/lo
__device__ __half g_hh[NP * HH], g_hl[NP * HH];   // BN(h) fp16 hi/lo
__device__ __half g_ah[NP * HH], g_al[NP * HH];   // agg fp16 hi/lo
__device__ __half g_w[8 * MM];                    // weights, single fp16
__device__ float g_scale[NN];
__device__ int   g_degi[NN];         // zeroed per-node inside k_agg2
__device__ int   g_rowptr[NN + 1];
__device__ int   g_fill[NN];
__device__ int   g_esrc[EE];
__device__ float g_sum[HH];
__device__ float g_sq[HH];
__device__ float g_bnA[HH];
__device__ float g_bnB[HH];

// ---------------- PTX helpers ----------------
__device__ __forceinline__ uint32_t cvta_s(const void* p) {
    return (uint32_t)__cvta_generic_to_shared(p);
}
__device__ __forceinline__ void cpa16(uint32_t dst, const void* src) {
    asm volatile("cp.async.cg.shared.global [%0], [%1], 16;\n" :: "r"(dst), "l"(src));
}
__device__ __forceinline__ void ldm_x4(uint32_t& r0, uint32_t& r1, uint32_t& r2, uint32_t& r3, uint32_t addr) {
    asm volatile("ldmatrix.sync.aligned.m8n8.x4.shared.b16 {%0,%1,%2,%3}, [%4];\n"
                 : "=r"(r0), "=r"(r1), "=r"(r2), "=r"(r3) : "r"(addr));
}
__device__ __forceinline__ void mma_f16(float* d, uint32_t a0, uint32_t a1, uint32_t a2, uint32_t a3,
                                        uint32_t b0, uint32_t b1) {
    asm volatile("mma.sync.aligned.m16n8k16.row.col.f32.f16.f16.f32 "
                 "{%0,%1,%2,%3}, {%4,%5,%6,%7}, {%8,%9}, {%0,%1,%2,%3};\n"
                 : "+f"(d[0]), "+f"(d[1]), "+f"(d[2]), "+f"(d[3])
                 : "r"(a0), "r"(a1), "r"(a2), "r"(a3), "r"(b0), "r"(b1));
}

// ---------------- fused prep: pads, x split, weight rounding, stats zero --------
#define SPLITX (NN * HH)
#define SPLITW (8 * MM)
#define PADSZ  ((NP - NN) * HH)
#define PREP_TOTAL (SPLITX + SPLITW + PADSZ + HH)

__global__ void k_prep(const float* __restrict__ x,
                       const float* __restrict__ Wpr, const float* __restrict__ Wpw,
                       const float* __restrict__ Wrel, const float* __restrict__ Wroot) {
    int i = blockIdx.x * blockDim.x + threadIdx.x;
    if (i < SPLITX) {
        float v = x[i];
        __half h = __float2half(v);
        g_xh[i] = h;
        g_xl[i] = __float2half(v - __half2float(h));
        return;
    }
    i -= SPLITX;
    if (i < SPLITW) {
        int w = i >> 18;
        int off = i & (MM - 1);
        const float* src;
        if (w == 0) src = Wpr + off;
        else if (w == 1) src = Wpw + off;
        else if (w < 5) src = Wrel + (size_t)(w - 2) * MM + off;
        else src = Wroot + (size_t)(w - 5) * MM + off;
        g_w[i] = __float2half(*src);
        return;
    }
    i -= SPLITW;
    if (i < PADSZ) {
        int off = NN * HH + i;
        __half z = __float2half(0.0f);
        g_xh[off] = z; g_xl[off] = z;
        g_hh[off] = z; g_hl[off] = z;
        g_ah[off] = z; g_al[off] = z;
        return;
    }
    i -= PADSZ;
    if (i < HH) { g_sum[i] = 0.f; g_sq[i] = 0.f; }
}

// ---------------- CSR build ----------------
__global__ void k_deg(const int* __restrict__ ei) {
    int e = blockIdx.x * blockDim.x + threadIdx.x;
    if (e < EE) atomicAdd(&g_degi[ei[EE + e]], 1);
}
__global__ void k_scanscale() {
    __shared__ int warp_part[32];
    __shared__ int carry;
    int t = threadIdx.x;
    int lane = t & 31, w = t >> 5;
    if (t == 0) carry = 0;
    __syncthreads();
    for (int base = 0; base < NN; base += 1024) {
        int i = base + t;
        int v = (i < NN) ? g_degi[i] : 0;
        if (i < NN) g_scale[i] = 1.0f / (float)(v > 0 ? v : 1);
        int s = v;
#pragma unroll
        for (int o = 1; o < 32; o <<= 1) {
            int u = __shfl_up_sync(0xffffffff, s, o);
            if (lane >= o) s += u;
        }
        if (lane == 31) warp_part[w] = s;
        __syncthreads();
        if (w == 0) {
            int p = warp_part[lane];
#pragma unroll
            for (int o = 1; o < 32; o <<= 1) {
                int u = __shfl_up_sync(0xffffffff, p, o);
                if (lane >= o) p += u;
            }
            warp_part[lane] = p;
        }
        __syncthreads();
        int add = (w > 0) ? warp_part[w - 1] : 0;
        int inc = s + add + carry;
        if (i < NN) g_rowptr[i + 1] = inc;
        __syncthreads();
        if (t == 1023) carry = inc;
        __syncthreads();
    }
    if (t == 0) g_rowptr[0] = 0;
}
__global__ void k_fill(const int* __restrict__ ei) {
    int e = blockIdx.x * blockDim.x + threadIdx.x;
    if (e < EE) {
        int dst = ei[EE + e];
        int pos = g_rowptr[dst] + atomicAdd(&g_fill[dst], 1);
        g_esrc[pos] = ei[e];
    }
}

// ---------------- mean aggregation + optional BN affine + fp16 split ----------------
__global__ void k_agg2(const float* __restrict__ h, int useBN,
                       __half* __restrict__ oh, __half* __restrict__ ol,
                       float* __restrict__ of) {
    int node = blockIdx.x;
    int t = threadIdx.x;
    if (t == 0) { g_degi[node] = 0; g_fill[node] = 0; }   // reset for next replay
    int s = g_rowptr[node];
    int e = g_rowptr[node + 1];
    float ax = 0.f, ay = 0.f, az = 0.f, aw = 0.f;
    int j = s;
    for (; j + 1 < e; j += 2) {
        int s0 = g_esrc[j];
        int s1 = g_esrc[j + 1];
        float4 v0 = ((const float4*)(h + (size_t)s0 * HH))[t];
        float4 v1 = ((const float4*)(h + (size_t)s1 * HH))[t];
        ax += v0.x + v1.x; ay += v0.y + v1.y;
        az += v0.z + v1.z; aw += v0.w + v1.w;
    }
    if (j < e) {
        int s0 = g_esrc[j];
        float4 v0 = ((const float4*)(h + (size_t)s0 * HH))[t];
        ax += v0.x; ay += v0.y; az += v0.z; aw += v0.w;
    }
    float sc = g_scale[node];
    ax *= sc; ay *= sc; az *= sc; aw *= sc;
    if (useBN) {
        float4 a = ((const float4*)g_bnA)[t];
        float4 b = ((const float4*)g_bnB)[t];
        ax = ax * a.x + b.x; ay = ay * a.y + b.y;
        az = az * a.z + b.z; aw = aw * a.w + b.w;
    }
    if (of) {
        ((float4*)(of + (size_t)node * HH))[t] = make_float4(ax, ay, az, aw);
    }
    if (oh) {
        __half hx = __float2half(ax), hy = __float2half(ay);
        __half hz = __float2half(az), hw = __float2half(aw);
        __half lx = __float2half(ax - __half2float(hx));
        __half ly = __float2half(ay - __half2float(hy));
        __half lz = __float2half(az - __half2float(hz));
        __half lw = __float2half(aw - __half2float(hw));
        __half2* ph = (__half2*)(oh + (size_t)node * HH);
        __half2* pl = (__half2*)(ol + (size_t)node * HH);
        ph[t * 2 + 0] = __halves2half2(hx, hy);
        ph[t * 2 + 1] = __halves2half2(hz, hw);
        pl[t * 2 + 0] = __halves2half2(lx, ly);
        pl[t * 2 + 1] = __halves2half2(lz, lw);
    }
}

// ---------------- mma.sync dual GEMM, 96x128 tile, BK=32, fp16 2-term ----------
// A split fp16 hi/lo, W single fp16. acc += Ah@W^T + Al@W^T.
// nk=32: dual (A1,W1 for kt<16; A2,W2 for kt>=16). nk=16: single pair.
#define LDS 40
#define A_HALVES (96 * LDS)                       // 3840
#define B_HALVES (128 * LDS)                      // 5120
#define STAGE_HALVES (2 * A_HALVES + B_HALVES)    // 12800 halves = 25600 B
#define GEMM_SMEM (2 * STAGE_HALVES * 2)          // 51200 B

__global__ __launch_bounds__(192, 3)
void k_gemm7(const __half* __restrict__ a1h, const __half* __restrict__ a1l,
             const __half* __restrict__ a2h, const __half* __restrict__ a2l,
             const __half* __restrict__ w1, const __half* __restrict__ w2,
             float* __restrict__ C, const float* __restrict__ Cin,
             int nk, int finalize) {
    extern __shared__ __half dsm[];

    const int tx = threadIdx.x;
    const int lane = tx & 31;
    const int warp = tx >> 5;
    const int wm = (warp % 3) * 32;
    const int wn = (warp / 3) * 64;
    const int m0 = blockIdx.y * 96;
    const int n0 = blockIdx.x * 128;

    float acc[2][8][4];
#pragma unroll
    for (int i = 0; i < 2; i++)
#pragma unroll
        for (int j = 0; j < 8; j++)
#pragma unroll
            for (int q = 0; q < 4; q++) acc[i][j][q] = 0.f;

    auto loadStage = [&](int kt, int st) {
        const __half* Ah = (kt < 16) ? a1h : a2h;
        const __half* Al = (kt < 16) ? a1l : a2l;
        const __half* W  = (kt < 16) ? w1 : w2;
        int k0 = (kt & 15) * 32;
        __half* base = dsm + st * STAGE_HALVES;
#pragma unroll
        for (int rep = 0; rep < 2; rep++) {
            int idx = tx + rep * 192;
            int row = idx >> 2;
            int seg = (idx & 3) * 8;
            size_t ao = (size_t)(m0 + row) * HH + k0 + seg;
            uint32_t so = (uint32_t)(row * LDS + seg);
            cpa16(cvta_s(base + so), Ah + ao);
            cpa16(cvta_s(base + A_HALVES + so), Al + ao);
        }
#pragma unroll
        for (int rep = 0; rep < 3; rep++) {
            int idx = tx + rep * 192;
            if (idx < 512) {
                int row = idx >> 2;
                int seg = (idx & 3) * 8;
                size_t wo = (size_t)(n0 + row) * HH + k0 + seg;
                uint32_t so = (uint32_t)(row * LDS + seg);
                cpa16(cvta_s(base + 2 * A_HALVES + so), W + wo);
            }
        }
        asm volatile("cp.async.commit_group;\n");
    };

    loadStage(0, 0);

    for (int kt = 0; kt < nk; ++kt) {
        int st = kt & 1;
        if (kt + 1 < nk) {
            loadStage(kt + 1, st ^ 1);
            asm volatile("cp.async.wait_group 1;\n" ::: "memory");
        } else {
            asm volatile("cp.async.wait_group 0;\n" ::: "memory");
        }
        __syncthreads();

        __half* base = dsm + st * STAGE_HALVES;
        __half* sAh = base;
        __half* sAl = base + A_HALVES;
        __half* sW  = base + 2 * A_HALVES;

#pragma unroll
        for (int ks = 0; ks < 2; ks++) {
            int kc = ks * 16;
            uint32_t ah[2][4], al[2][4];
#pragma unroll
            for (int i = 0; i < 2; i++) {
                int r = wm + i * 16 + (lane & 15);
                int c = kc + ((lane >> 4) & 1) * 8;
                ldm_x4(ah[i][0], ah[i][1], ah[i][2], ah[i][3], cvta_s(sAh + r * LDS + c));
                ldm_x4(al[i][0], al[i][1], al[i][2], al[i][3], cvta_s(sAl + r * LDS + c));
            }
#pragma unroll
            for (int jj = 0; jj < 4; jj++) {
                int r = wn + jj * 16 + (lane & 7) + ((lane >> 4) & 1) * 8;
                int c = kc + ((lane >> 3) & 1) * 8;
                uint32_t bh[4];
                ldm_x4(bh[0], bh[1], bh[2], bh[3], cvta_s(sW + r * LDS + c));
#pragma unroll
                for (int i = 0; i < 2; i++) {
                    float* a0 = acc[i][jj * 2 + 0];
                    float* a1 = acc[i][jj * 2 + 1];
                    mma_f16(a0, ah[i][0], ah[i][1], ah[i][2], ah[i][3], bh[0], bh[1]);
                    mma_f16(a0, al[i][0], al[i][1], al[i][2], al[i][3], bh[0], bh[1]);
                    mma_f16(a1, ah[i][0], ah[i][1], ah[i][2], ah[i][3], bh[2], bh[3]);
                    mma_f16(a1, al[i][0], al[i][1], al[i][2], al[i][3], bh[2], bh[3]);
                }
            }
        }
        __syncthreads();
    }

    if (!finalize) {
#pragma unroll
        for (int j = 0; j < 8; j++) {
#pragma unroll
            for (int i = 0; i < 2; i++) {
                int r = m0 + wm + i * 16 + (lane >> 2);
                int c = n0 + wn + j * 8 + (lane & 3) * 2;
                *(float2*)(C + (size_t)r * HH + c) = make_float2(acc[i][j][0], acc[i][j][1]);
                *(float2*)(C + (size_t)(r + 8) * HH + c) = make_float2(acc[i][j][2], acc[i][j][3]);
            }
        }
        return;
    }

    // finalize: (+Cin) + relu + store + fused BN column stats
#pragma unroll
    for (int j = 0; j < 8; j++) {
        float s0 = 0.f, s1 = 0.f, q0 = 0.f, q1 = 0.f;
#pragma unroll
        for (int i = 0; i < 2; i++) {
            int r = m0 + wm + i * 16 + (lane >> 2);
            int c = n0 + wn + j * 8 + (lane & 3) * 2;
            float v00 = acc[i][j][0], v01 = acc[i][j][1];
            float v10 = acc[i][j][2], v11 = acc[i][j][3];
            if (Cin) {
                float2 p0 = *(const float2*)(Cin + (size_t)r * HH + c);
                float2 p1 = *(const float2*)(Cin + (size_t)(r + 8) * HH + c);
                v00 += p0.x; v01 += p0.y; v10 += p1.x; v11 += p1.y;
            }
            v00 = fmaxf(v00, 0.f); v01 = fmaxf(v01, 0.f);
            v10 = fmaxf(v10, 0.f); v11 = fmaxf(v11, 0.f);
            *(float2*)(C + (size_t)r * HH + c) = make_float2(v00, v01);
            *(float2*)(C + (size_t)(r + 8) * HH + c) = make_float2(v10, v11);
            s0 += v00 + v10; s1 += v01 + v11;
            q0 += v00 * v00 + v10 * v10; q1 += v01 * v01 + v11 * v11;
        }
#pragma unroll
        for (int o = 16; o >= 4; o >>= 1) {
            s0 += __shfl_down_sync(0xffffffff, s0, o);
            s1 += __shfl_down_sync(0xffffffff, s1, o);
            q0 += __shfl_down_sync(0xffffffff, q0, o);
            q1 += __shfl_down_sync(0xffffffff, q1, o);
        }
        if (lane < 4) {
            int cc = n0 + wn + j * 8 + lane * 2;
            atomicAdd(&g_sum[cc], s0);
            atomicAdd(&g_sum[cc + 1], s1);
            atomicAdd(&g_sq[cc], q0);
            atomicAdd(&g_sq[cc + 1], q1);
        }
    }
}

// ---------------- BatchNorm finalize (reads + self-zeroes stats) ----------------
__global__ void k_bnfin(const float* __restrict__ gamma, const float* __restrict__ beta) {
    int f = threadIdx.x;
    float s = g_sum[f];
    float q = g_sq[f];
    g_sum[f] = 0.f;
    g_sq[f] = 0.f;
    float mu = s / (float)NN;
    float var = q / (float)NN - mu * mu;
    float inv = rsqrtf(var + BN_EPS);
    float sc = gamma[f] * inv;
    g_bnA[f] = sc;
    g_bnB[f] = beta[f] - mu * sc;
}
// BN apply + fp16 hi/lo split (root operand only)
__global__ void k_bnapply2(const float* __restrict__ h,
                           __half* __restrict__ hh, __half* __restrict__ hl) {
    int idx = blockIdx.x * blockDim.x + threadIdx.x;
    if (idx >= NN * HH / 4) return;
    int f4 = idx & (HH / 4 - 1);
    float4 v = ((const float4*)h)[idx];
    float4 a = ((const float4*)g_bnA)[f4];
    float4 b = ((const float4*)g_bnB)[f4];
    v.x = v.x * a.x + b.x;
    v.y = v.y * a.y + b.y;
    v.z = v.z * a.z + b.z;
    v.w = v.w * a.w + b.w;
    __half hx = __float2half(v.x), hy = __float2half(v.y);
    __half hz = __float2half(v.z), hw = __float2half(v.w);
    __half lx = __float2half(v.x - __half2float(hx));
    __half ly = __float2half(v.y - __half2float(hy));
    __half lz = __float2half(v.z - __half2float(hz));
    __half lw = __float2half(v.w - __half2float(hw));
    ((__half2*)hh)[idx * 2 + 0] = __halves2half2(hx, hy);
    ((__half2*)hh)[idx * 2 + 1] = __halves2half2(hz, hw);
    ((__half2*)hl)[idx * 2 + 0] = __halves2half2(lx, ly);
    ((__half2*)hl)[idx * 2 + 1] = __halves2half2(lz, lw);
}

// ---------------- final conv (C=10) + log_softmax (fp32 exact) ----------------
__global__ __launch_bounds__(320)
void k_final(const float* __restrict__ agg, const float* __restrict__ r,
             const float* __restrict__ Wr, const float* __restrict__ Ww,
             float* __restrict__ out) {
    __shared__ float sa[HH];
    __shared__ float sh[HH];
    __shared__ float slog[CC];
    __shared__ float sLse;
    int node = blockIdx.x;
    int t = threadIdx.x;
    for (int i = t; i < HH; i += 320) {
        sa[i] = agg[(size_t)node * HH + i];
        sh[i] = r[(size_t)node * HH + i] * g_bnA[i] + g_bnB[i];
    }
    __syncthreads();
    int w = t >> 5, lane = t & 31;
    float s = 0.f;
    for (int k = lane; k < HH; k += 32)
        s += sa[k] * Wr[w * HH + k] + sh[k] * Ww[w * HH + k];
#pragma unroll
    for (int o = 16; o; o >>= 1) s += __shfl_down_sync(0xffffffff, s, o);
    if (lane == 0) slog[w] = s;
    __syncthreads();
    if (t == 0) {
        float mx = slog[0];
        for (int c = 1; c < CC; c++) mx = fmaxf(mx, slog[c]);
        float sum = 0.f;
        for (int c = 0; c < CC; c++) sum += expf(slog[c] - mx);
        sLse = mx + logf(sum);
    }
    __syncthreads();
    if (t < CC) out[(size_t)node * CC + t] = slog[t] - sLse;
}

// ---------------- launch ----------------
extern "C" void kernel_launch(void* const* d_in, const int* in_sizes, int n_in,
                              void* d_out, int out_size) {
    const float* x     = (const float*)d_in[0];
    const int*   ei    = (const int*)d_in[1];
    const float* Wpr   = (const float*)d_in[2];
    const float* Wpw   = (const float*)d_in[3];
    const float* Wrel  = (const float*)d_in[4];
    const float* Wroot = (const float*)d_in[5];
    const float* gamma = (const float*)d_in[6];
    const float* beta  = (const float*)d_in[7];
    const float* Wfr   = (const float*)d_in[8];
    const float* Wfw   = (const float*)d_in[9];
    float* out = (float*)d_out;

    static float *p_h1 = nullptr, *p_h2 = nullptr, *p_agg = nullptr;
    static __half *p_xh, *p_xl, *p_hh, *p_hl, *p_ah, *p_al, *p_w;
    if (!p_h1) {
        cudaGetSymbolAddress((void**)&p_h1, g_h1);
        cudaGetSymbolAddress((void**)&p_h2, g_h2);
        cudaGetSymbolAddress((void**)&p_agg, g_agg);
        cudaGetSymbolAddress((void**)&p_xh, g_xh);
        cudaGetSymbolAddress((void**)&p_xl, g_xl);
        cudaGetSymbolAddress((void**)&p_hh, g_hh);
        cudaGetSymbolAddress((void**)&p_hl, g_hl);
        cudaGetSymbolAddress((void**)&p_ah, g_ah);
        cudaGetSymbolAddress((void**)&p_al, g_al);
        cudaGetSymbolAddress((void**)&p_w, g_w);
        cudaFuncSetAttribute(k_gemm7, cudaFuncAttributeMaxDynamicSharedMemorySize, GEMM_SMEM);
    }

    dim3 gemmGrid(HH / 128, NP / 96);   // (4, 106) = 424 CTAs
    int eb = (EE + 255) / 256;
    int apb = (NN * HH / 4 + 255) / 256;
    int prepb = (PREP_TOTAL + 255) / 256;

    // 1: deg, 2: prep, 3: scan+scale, 4: GEMM(root half of proj) <- profiled window
    k_deg<<<eb, 256>>>(ei);
    k_prep<<<prepb, 256>>>(x, Wpr, Wpw, Wrel, Wroot);
    k_scanscale<<<1, 1024>>>();
    k_gemm7<<<gemmGrid, 192, GEMM_SMEM>>>(p_xh, p_xl, p_xh, p_xl,
                                          p_w + 1 * MM, p_w + 1 * MM,
                                          p_h1, nullptr, 16, 0);   // raw x@Wpw^T
    // 5: fill, 6: agg(x), 7: GEMM(rel half, finalize: +agg@Wpr^T, relu, stats)
    k_fill<<<eb, 256>>>(ei);
    k_agg2<<<NN, 128>>>(x, 0, p_ah, p_al, nullptr);
    k_gemm7<<<gemmGrid, 192, GEMM_SMEM>>>(p_ah, p_al, p_ah, p_al,
                                          p_w + 0 * MM, p_w + 0 * MM,
                                          p_h1, p_h1, 16, 1);
    k_bnfin<<<1, HH>>>(gamma, beta);
    k_bnapply2<<<apb, 256>>>(p_h1, p_hh, p_hl);

    float* cur = p_h1;
    float* nxt = p_h2;
    for (int l = 0; l < 3; ++l) {
        k_agg2<<<NN, 128>>>(cur, 1, p_ah, p_al, nullptr);
        k_gemm7<<<gemmGrid, 192, GEMM_SMEM>>>(p_ah, p_al, p_hh, p_hl,
                                              p_w + (2 + l) * MM, p_w + (5 + l) * MM,
                                              nxt, nullptr, 32, 1);
        k_bnfin<<<1, HH>>>(gamma + (size_t)(l + 1) * HH, beta + (size_t)(l + 1) * HH);
        if (l < 2)
            k_bnapply2<<<apb, 256>>>(nxt, p_hh, p_hl);
        float* tmp = cur; cur = nxt; nxt = tmp;
    }

    k_agg2<<<NN, 128>>>(cur, 1, nullptr, nullptr, p_agg);
    k_final<<<NN, 320>>>(p_agg, cur, Wfr, Wfw, out);
}

// round 12
// speedup vs baseline: 2.6691x; 1.3128x over previous
#include <cuda_runtime.h>
#include <cuda_fp16.h>
#include <math.h>
#include <stdint.h>

#define NN 10000
#define NP 10176            // 106 * 96
#define EE 160000
#define HH 512
#define CC 10
#define MM (HH * HH)
#define BN_EPS 1e-5f

// ---------------- device scratch ----------------
__device__ float g_h1[NP * HH];      // raw relu(conv) output (pre-BN)
__device__ float g_h2[NP * HH];
__device__ float g_agg[NP * HH];
__device__ __half g_x16[NP * HH];    // x fp16
__device__ __half g_h16[NP * HH];    // BN(h) fp16
__device__ __half g_a16[NP * HH];    // agg fp16
__device__ __half g_w[8 * MM];       // weights fp16
__device__ float g_scale[NN];
__device__ int   g_degi[NN];         // zeroed per-node inside k_agg2
__device__ int   g_rowptr[NN + 1];
__device__ int   g_fill[NN];
__device__ int   g_esrc[EE];
__device__ float g_sum[HH];
__device__ float g_sq[HH];
__device__ float g_bnA[HH];
__device__ float g_bnB[HH];

// ---------------- PTX helpers ----------------
__device__ __forceinline__ uint32_t cvta_s(const void* p) {
    return (uint32_t)__cvta_generic_to_shared(p);
}
__device__ __forceinline__ void cpa16(uint32_t dst, const void* src) {
    asm volatile("cp.async.cg.shared.global [%0], [%1], 16;\n" :: "r"(dst), "l"(src));
}
__device__ __forceinline__ void ldm_x4(uint32_t& r0, uint32_t& r1, uint32_t& r2, uint32_t& r3, uint32_t addr) {
    asm volatile("ldmatrix.sync.aligned.m8n8.x4.shared.b16 {%0,%1,%2,%3}, [%4];\n"
                 : "=r"(r0), "=r"(r1), "=r"(r2), "=r"(r3) : "r"(addr));
}
__device__ __forceinline__ void mma_f16(float* d, uint32_t a0, uint32_t a1, uint32_t a2, uint32_t a3,
                                        uint32_t b0, uint32_t b1) {
    asm volatile("mma.sync.aligned.m16n8k16.row.col.f32.f16.f16.f32 "
                 "{%0,%1,%2,%3}, {%4,%5,%6,%7}, {%8,%9}, {%0,%1,%2,%3};\n"
                 : "+f"(d[0]), "+f"(d[1]), "+f"(d[2]), "+f"(d[3])
                 : "r"(a0), "r"(a1), "r"(a2), "r"(a3), "r"(b0), "r"(b1));
}

// ---------------- fused prep: pads, x round, weight round, stats zero --------
#define SPLITX (NN * HH)
#define SPLITW (8 * MM)
#define PADSZ  ((NP - NN) * HH)
#define PREP_TOTAL (SPLITX + SPLITW + PADSZ + HH)

__global__ void k_prep(const float* __restrict__ x,
                       const float* __restrict__ Wpr, const float* __restrict__ Wpw,
                       const float* __restrict__ Wrel, const float* __restrict__ Wroot) {
    int i = blockIdx.x * blockDim.x + threadIdx.x;
    if (i < SPLITX) {
        g_x16[i] = __float2half(x[i]);
        return;
    }
    i -= SPLITX;
    if (i < SPLITW) {
        int w = i >> 18;
        int off = i & (MM - 1);
        const float* src;
        if (w == 0) src = Wpr + off;
        else if (w == 1) src = Wpw + off;
        else if (w < 5) src = Wrel + (size_t)(w - 2) * MM + off;
        else src = Wroot + (size_t)(w - 5) * MM + off;
        g_w[i] = __float2half(*src);
        return;
    }
    i -= SPLITW;
    if (i < PADSZ) {
        int off = NN * HH + i;
        __half z = __float2half(0.0f);
        g_x16[off] = z;
        g_h16[off] = z;
        g_a16[off] = z;
        return;
    }
    i -= PADSZ;
    if (i < HH) { g_sum[i] = 0.f; g_sq[i] = 0.f; }
}

// ---------------- CSR build ----------------
__global__ void k_deg(const int* __restrict__ ei) {
    int e = blockIdx.x * blockDim.x + threadIdx.x;
    if (e < EE) atomicAdd(&g_degi[ei[EE + e]], 1);
}
__global__ void k_scanscale() {
    __shared__ int warp_part[32];
    __shared__ int carry;
    int t = threadIdx.x;
    int lane = t & 31, w = t >> 5;
    if (t == 0) carry = 0;
    __syncthreads();
    for (int base = 0; base < NN; base += 1024) {
        int i = base + t;
        int v = (i < NN) ? g_degi[i] : 0;
        if (i < NN) g_scale[i] = 1.0f / (float)(v > 0 ? v : 1);
        int s = v;
#pragma unroll
        for (int o = 1; o < 32; o <<= 1) {
            int u = __shfl_up_sync(0xffffffff, s, o);
            if (lane >= o) s += u;
        }
        if (lane == 31) warp_part[w] = s;
        __syncthreads();
        if (w == 0) {
            int p = warp_part[lane];
#pragma unroll
            for (int o = 1; o < 32; o <<= 1) {
                int u = __shfl_up_sync(0xffffffff, p, o);
                if (lane >= o) p += u;
            }
            warp_part[lane] = p;
        }
        __syncthreads();
        int add = (w > 0) ? warp_part[w - 1] : 0;
        int inc = s + add + carry;
        if (i < NN) g_rowptr[i + 1] = inc;
        __syncthreads();
        if (t == 1023) carry = inc;
        __syncthreads();
    }
    if (t == 0) g_rowptr[0] = 0;
}
__global__ void k_fill(const int* __restrict__ ei) {
    int e = blockIdx.x * blockDim.x + threadIdx.x;
    if (e < EE) {
        int dst = ei[EE + e];
        int pos = g_rowptr[dst] + atomicAdd(&g_fill[dst], 1);
        g_esrc[pos] = ei[e];
    }
}

// ---------------- mean aggregation + optional BN affine + fp16 round ----------------
__global__ void k_agg2(const float* __restrict__ h, int useBN,
                       __half* __restrict__ oh, float* __restrict__ of) {
    int node = blockIdx.x;
    int t = threadIdx.x;
    if (t == 0) { g_degi[node] = 0; g_fill[node] = 0; }   // reset for next replay
    int s = g_rowptr[node];
    int e = g_rowptr[node + 1];
    float ax = 0.f, ay = 0.f, az = 0.f, aw = 0.f;
    int j = s;
    for (; j + 1 < e; j += 2) {
        int s0 = g_esrc[j];
        int s1 = g_esrc[j + 1];
        float4 v0 = ((const float4*)(h + (size_t)s0 * HH))[t];
        float4 v1 = ((const float4*)(h + (size_t)s1 * HH))[t];
        ax += v0.x + v1.x; ay += v0.y + v1.y;
        az += v0.z + v1.z; aw += v0.w + v1.w;
    }
    if (j < e) {
        int s0 = g_esrc[j];
        float4 v0 = ((const float4*)(h + (size_t)s0 * HH))[t];
        ax += v0.x; ay += v0.y; az += v0.z; aw += v0.w;
    }
    float sc = g_scale[node];
    ax *= sc; ay *= sc; az *= sc; aw *= sc;
    if (useBN) {
        float4 a = ((const float4*)g_bnA)[t];
        float4 b = ((const float4*)g_bnB)[t];
        ax = ax * a.x + b.x; ay = ay * a.y + b.y;
        az = az * a.z + b.z; aw = aw * a.w + b.w;
    }
    if (of) {
        ((float4*)(of + (size_t)node * HH))[t] = make_float4(ax, ay, az, aw);
    }
    if (oh) {
        __half2* ph = (__half2*)(oh + (size_t)node * HH);
        ph[t * 2 + 0] = __halves2half2(__float2half(ax), __float2half(ay));
        ph[t * 2 + 1] = __halves2half2(__float2half(az), __float2half(aw));
    }
}

// ---------------- mma.sync dual GEMM, 96x128 tile, BK=32, fp16 single-term ----
// acc += A@W^T. nk=32: dual (A1,W1 kt<16; A2,W2 kt>=16). nk=16: single pair.
#define LDS 40
#define A_HALVES (96 * LDS)                       // 3840
#define B_HALVES (128 * LDS)                      // 5120
#define STAGE_HALVES (A_HALVES + B_HALVES)        // 8960 halves = 17920 B
#define GEMM_SMEM (2 * STAGE_HALVES * 2)          // 35840 B

__global__ __launch_bounds__(192, 3)
void k_gemm8(const __half* __restrict__ a1, const __half* __restrict__ a2,
             const __half* __restrict__ w1, const __half* __restrict__ w2,
             float* __restrict__ C, const float* __restrict__ Cin,
             int nk, int finalize) {
    extern __shared__ __half dsm[];

    const int tx = threadIdx.x;
    const int lane = tx & 31;
    const int warp = tx >> 5;
    const int wm = (warp % 3) * 32;
    const int wn = (warp / 3) * 64;
    const int m0 = blockIdx.y * 96;
    const int n0 = blockIdx.x * 128;

    float acc[2][8][4];
#pragma unroll
    for (int i = 0; i < 2; i++)
#pragma unroll
        for (int j = 0; j < 8; j++)
#pragma unroll
            for (int q = 0; q < 4; q++) acc[i][j][q] = 0.f;

    auto loadStage = [&](int kt, int st) {
        const __half* A = (kt < 16) ? a1 : a2;
        const __half* W = (kt < 16) ? w1 : w2;
        int k0 = (kt & 15) * 32;
        __half* base = dsm + st * STAGE_HALVES;
#pragma unroll
        for (int rep = 0; rep < 2; rep++) {
            int idx = tx + rep * 192;
            int row = idx >> 2;
            int seg = (idx & 3) * 8;
            size_t ao = (size_t)(m0 + row) * HH + k0 + seg;
            uint32_t so = (uint32_t)(row * LDS + seg);
            cpa16(cvta_s(base + so), A + ao);
        }
#pragma unroll
        for (int rep = 0; rep < 3; rep++) {
            int idx = tx + rep * 192;
            if (idx < 512) {
                int row = idx >> 2;
                int seg = (idx & 3) * 8;
                size_t wo = (size_t)(n0 + row) * HH + k0 + seg;
                uint32_t so = (uint32_t)(row * LDS + seg);
                cpa16(cvta_s(base + A_HALVES + so), W + wo);
            }
        }
        asm volatile("cp.async.commit_group;\n");
    };

    loadStage(0, 0);

    for (int kt = 0; kt < nk; ++kt) {
        int st = kt & 1;
        if (kt + 1 < nk) {
            loadStage(kt + 1, st ^ 1);
            asm volatile("cp.async.wait_group 1;\n" ::: "memory");
        } else {
            asm volatile("cp.async.wait_group 0;\n" ::: "memory");
        }
        __syncthreads();

        __half* base = dsm + st * STAGE_HALVES;
        __half* sA = base;
        __half* sW = base + A_HALVES;

#pragma unroll
        for (int ks = 0; ks < 2; ks++) {
            int kc = ks * 16;
            uint32_t ah[2][4];
#pragma unroll
            for (int i = 0; i < 2; i++) {
                int r = wm + i * 16 + (lane & 15);
                int c = kc + ((lane >> 4) & 1) * 8;
                ldm_x4(ah[i][0], ah[i][1], ah[i][2], ah[i][3], cvta_s(sA + r * LDS + c));
            }
#pragma unroll
            for (int jj = 0; jj < 4; jj++) {
                int r = wn + jj * 16 + (lane & 7) + ((lane >> 4) & 1) * 8;
                int c = kc + ((lane >> 3) & 1) * 8;
                uint32_t bh[4];
                ldm_x4(bh[0], bh[1], bh[2], bh[3], cvta_s(sW + r * LDS + c));
#pragma unroll
                for (int i = 0; i < 2; i++) {
                    mma_f16(acc[i][jj * 2 + 0], ah[i][0], ah[i][1], ah[i][2], ah[i][3], bh[0], bh[1]);
                    mma_f16(acc[i][jj * 2 + 1], ah[i][0], ah[i][1], ah[i][2], ah[i][3], bh[2], bh[3]);
                }
            }
        }
        __syncthreads();
    }

    if (!finalize) {
#pragma unroll
        for (int j = 0; j < 8; j++) {
#pragma unroll
            for (int i = 0; i < 2; i++) {
                int r = m0 + wm + i * 16 + (lane >> 2);
                int c = n0 + wn + j * 8 + (lane & 3) * 2;
                *(float2*)(C + (size_t)r * HH + c) = make_float2(acc[i][j][0], acc[i][j][1]);
                *(float2*)(C + (size_t)(r + 8) * HH + c) = make_float2(acc[i][j][2], acc[i][j][3]);
            }
        }
        return;
    }

    // finalize: (+Cin) + relu + store + fused BN column stats
#pragma unroll
    for (int j = 0; j < 8; j++) {
        float s0 = 0.f, s1 = 0.f, q0 = 0.f, q1 = 0.f;
#pragma unroll
        for (int i = 0; i < 2; i++) {
            int r = m0 + wm + i * 16 + (lane >> 2);
            int c = n0 + wn + j * 8 + (lane & 3) * 2;
            float v00 = acc[i][j][0], v01 = acc[i][j][1];
            float v10 = acc[i][j][2], v11 = acc[i][j][3];
            if (Cin) {
                float2 p0 = *(const float2*)(Cin + (size_t)r * HH + c);
                float2 p1 = *(const float2*)(Cin + (size_t)(r + 8) * HH + c);
                v00 += p0.x; v01 += p0.y; v10 += p1.x; v11 += p1.y;
            }
            v00 = fmaxf(v00, 0.f); v01 = fmaxf(v01, 0.f);
            v10 = fmaxf(v10, 0.f); v11 = fmaxf(v11, 0.f);
            *(float2*)(C + (size_t)r * HH + c) = make_float2(v00, v01);
            *(float2*)(C + (size_t)(r + 8) * HH + c) = make_float2(v10, v11);
            s0 += v00 + v10; s1 += v01 + v11;
            q0 += v00 * v00 + v10 * v10; q1 += v01 * v01 + v11 * v11;
        }
#pragma unroll
        for (int o = 16; o >= 4; o >>= 1) {
            s0 += __shfl_down_sync(0xffffffff, s0, o);
            s1 += __shfl_down_sync(0xffffffff, s1, o);
            q0 += __shfl_down_sync(0xffffffff, q0, o);
            q1 += __shfl_down_sync(0xffffffff, q1, o);
        }
        if (lane < 4) {
            int cc = n0 + wn + j * 8 + lane * 2;
            atomicAdd(&g_sum[cc], s0);
            atomicAdd(&g_sum[cc + 1], s1);
            atomicAdd(&g_sq[cc], q0);
            atomicAdd(&g_sq[cc + 1], q1);
        }
    }
}

// ---------------- BatchNorm finalize (reads + self-zeroes stats) ----------------
__global__ void k_bnfin(const float* __restrict__ gamma, const float* __restrict__ beta) {
    int f = threadIdx.x;
    float s = g_sum[f];
    float q = g_sq[f];
    g_sum[f] = 0.f;
    g_sq[f] = 0.f;
    float mu = s / (float)NN;
    float var = q / (float)NN - mu * mu;
    float inv = rsqrtf(var + BN_EPS);
    float sc = gamma[f] * inv;
    g_bnA[f] = sc;
    g_bnB[f] = beta[f] - mu * sc;
}
// BN apply + fp16 round (root operand only)
__global__ void k_bnapply2(const float* __restrict__ h, __half* __restrict__ hh) {
    int idx = blockIdx.x * blockDim.x + threadIdx.x;
    if (idx >= NN * HH / 4) return;
    int f4 = idx & (HH / 4 - 1);
    float4 v = ((const float4*)h)[idx];
    float4 a = ((const float4*)g_bnA)[f4];
    float4 b = ((const float4*)g_bnB)[f4];
    v.x = v.x * a.x + b.x;
    v.y = v.y * a.y + b.y;
    v.z = v.z * a.z + b.z;
    v.w = v.w * a.w + b.w;
    ((__half2*)hh)[idx * 2 + 0] = __halves2half2(__float2half(v.x), __float2half(v.y));
    ((__half2*)hh)[idx * 2 + 1] = __halves2half2(__float2half(v.z), __float2half(v.w));
}

// ---------------- final conv (C=10) + log_softmax (fp32 exact) ----------------
__global__ __launch_bounds__(320)
void k_final(const float* __restrict__ agg, const float* __restrict__ r,
             const float* __restrict__ Wr, const float* __restrict__ Ww,
             float* __restrict__ out) {
    __shared__ float sa[HH];
    __shared__ float sh[HH];
    __shared__ float slog[CC];
    __shared__ float sLse;
    int node = blockIdx.x;
    int t = threadIdx.x;
    for (int i = t; i < HH; i += 320) {
        sa[i] = agg[(size_t)node * HH + i];
        sh[i] = r[(size_t)node * HH + i] * g_bnA[i] + g_bnB[i];
    }
    __syncthreads();
    int w = t >> 5, lane = t & 31;
    float s = 0.f;
    for (int k = lane; k < HH; k += 32)
        s += sa[k] * Wr[w * HH + k] + sh[k] * Ww[w * HH + k];
#pragma unroll
    for (int o = 16; o; o >>= 1) s += __shfl_down_sync(0xffffffff, s, o);
    if (lane == 0) slog[w] = s;
    __syncthreads();
    if (t == 0) {
        float mx = slog[0];
        for (int c = 1; c < CC; c++) mx = fmaxf(mx, slog[c]);
        float sum = 0.f;
        for (int c = 0; c < CC; c++) sum += expf(slog[c] - mx);
        sLse = mx + logf(sum);
    }
    __syncthreads();
    if (t < CC) out[(size_t)node * CC + t] = slog[t] - sLse;
}

// ---------------- launch ----------------
extern "C" void kernel_launch(void* const* d_in, const int* in_sizes, int n_in,
                              void* d_out, int out_size) {
    const float* x     = (const float*)d_in[0];
    const int*   ei    = (const int*)d_in[1];
    const float* Wpr   = (const float*)d_in[2];
    const float* Wpw   = (const float*)d_in[3];
    const float* Wrel  = (const float*)d_in[4];
    const float* Wroot = (const float*)d_in[5];
    const float* gamma = (const float*)d_in[6];
    const float* beta  = (const float*)d_in[7];
    const float* Wfr   = (const float*)d_in[8];
    const float* Wfw   = (const float*)d_in[9];
    float* out = (float*)d_out;

    static float *p_h1 = nullptr, *p_h2 = nullptr, *p_agg = nullptr;
    static __half *p_x16, *p_h16, *p_a16, *p_w;
    if (!p_h1) {
        cudaGetSymbolAddress((void**)&p_h1, g_h1);
        cudaGetSymbolAddress((void**)&p_h2, g_h2);
        cudaGetSymbolAddress((void**)&p_agg, g_agg);
        cudaGetSymbolAddress((void**)&p_x16, g_x16);
        cudaGetSymbolAddress((void**)&p_h16, g_h16);
        cudaGetSymbolAddress((void**)&p_a16, g_a16);
        cudaGetSymbolAddress((void**)&p_w, g_w);
        cudaFuncSetAttribute(k_gemm8, cudaFuncAttributeMaxDynamicSharedMemorySize, GEMM_SMEM);
    }

    dim3 gemmGrid(HH / 128, NP / 96);   // (4, 106) = 424 CTAs
    int eb = (EE + 255) / 256;
    int apb = (NN * HH / 4 + 255) / 256;
    int prepb = (PREP_TOTAL + 255) / 256;

    // 1: deg, 2: prep, 3: scan+scale, 4: GEMM(root half of proj) <- profiled window
    k_deg<<<eb, 256>>>(ei);
    k_prep<<<prepb, 256>>>(x, Wpr, Wpw, Wrel, Wroot);
    k_scanscale<<<1, 1024>>>();
    k_gemm8<<<gemmGrid, 192, GEMM_SMEM>>>(p_x16, p_x16,
                                          p_w + 1 * MM, p_w + 1 * MM,
                                          p_h1, nullptr, 16, 0);   // raw x@Wpw^T
    // 5: fill, 6: agg(x), 7: GEMM(rel half, finalize: +agg@Wpr^T, relu, stats)
    k_fill<<<eb, 256>>>(ei);
    k_agg2<<<NN, 128>>>(x, 0, p_a16, nullptr);
    k_gemm8<<<gemmGrid, 192, GEMM_SMEM>>>(p_a16, p_a16,
                                          p_w + 0 * MM, p_w + 0 * MM,
                                          p_h1, p_h1, 16, 1);
    k_bnfin<<<1, HH>>>(gamma, beta);
    k_bnapply2<<<apb, 256>>>(p_h1, p_h16);

    float* cur = p_h1;
    float* nxt = p_h2;
    for (int l = 0; l < 3; ++l) {
        k_agg2<<<NN, 128>>>(cur, 1, p_a16, nullptr);
        k_gemm8<<<gemmGrid, 192, GEMM_SMEM>>>(p_a16, p_h16,
                                              p_w + (2 + l) * MM, p_w + (5 + l) * MM,
                                              nxt, nullptr, 32, 1);
        k_bnfin<<<1, HH>>>(gamma + (size_t)(l + 1) * HH, beta + (size_t)(l + 1) * HH);
        if (l < 2)
            k_bnapply2<<<apb, 256>>>(nxt, p_h16);
        float* tmp = cur; cur = nxt; nxt = tmp;
    }

    k_agg2<<<NN, 128>>>(cur, 1, nullptr, p_agg);
    k_final<<<NN, 320>>>(p_agg, cur, Wfr, Wfw, out);
}

// round 13
// speedup vs baseline: 2.7382x; 1.0259x over previous
#include <cuda_runtime.h>
#include <cuda_fp16.h>
#include <math.h>
#include <stdint.h>

#define NN 10000
#define NP 10176            // 106 * 96
#define EE 160000
#define HH 512
#define CC 10
#define MM (HH * HH)
#define BN_EPS 1e-5f

// ---------------- device scratch ----------------
__device__ float  g_part[NP * HH];   // fp32 partial (proj split only)
__device__ float  g_agg[NP * HH];    // fp32 BN'd agg for final layer
__device__ __half g_z1[NP * HH];     // raw relu z fp16 (ping)
__device__ __half g_z2[NP * HH];     // raw relu z fp16 (pong)
__device__ __half g_x16[NP * HH];    // x fp16
__device__ __half g_h16[NP * HH];    // BN(z) fp16 (root operand)
__device__ __half g_a16[NP * HH];    // agg fp16
__device__ __half g_w[8 * MM];       // weights fp16
__device__ float g_scale[NN];
__device__ int   g_degi[NN];         // zeroed per-node inside k_agg2
__device__ int   g_rowptr[NN + 1];
__device__ int   g_fill[NN];
__device__ int   g_esrc[EE];
__device__ float g_sum[HH];
__device__ float g_sq[HH];
__device__ float g_bnA[HH];
__device__ float g_bnB[HH];

// ---------------- PTX helpers ----------------
__device__ __forceinline__ uint32_t cvta_s(const void* p) {
    return (uint32_t)__cvta_generic_to_shared(p);
}
__device__ __forceinline__ void cpa16(uint32_t dst, const void* src) {
    asm volatile("cp.async.cg.shared.global [%0], [%1], 16;\n" :: "r"(dst), "l"(src));
}
__device__ __forceinline__ void ldm_x4(uint32_t& r0, uint32_t& r1, uint32_t& r2, uint32_t& r3, uint32_t addr) {
    asm volatile("ldmatrix.sync.aligned.m8n8.x4.shared.b16 {%0,%1,%2,%3}, [%4];\n"
                 : "=r"(r0), "=r"(r1), "=r"(r2), "=r"(r3) : "r"(addr));
}
__device__ __forceinline__ void mma_f16(float* d, uint32_t a0, uint32_t a1, uint32_t a2, uint32_t a3,
                                        uint32_t b0, uint32_t b1) {
    asm volatile("mma.sync.aligned.m16n8k16.row.col.f32.f16.f16.f32 "
                 "{%0,%1,%2,%3}, {%4,%5,%6,%7}, {%8,%9}, {%0,%1,%2,%3};\n"
                 : "+f"(d[0]), "+f"(d[1]), "+f"(d[2]), "+f"(d[3])
                 : "r"(a0), "r"(a1), "r"(a2), "r"(a3), "r"(b0), "r"(b1));
}

// ---------------- fused prep: pads, x round, weight round, stats zero --------
#define SPLITX (NN * HH)
#define SPLITW (8 * MM)
#define PADSZ  ((NP - NN) * HH)
#define PREP_TOTAL (SPLITX + SPLITW + PADSZ + HH)

__global__ void k_prep(const float* __restrict__ x,
                       const float* __restrict__ Wpr, const float* __restrict__ Wpw,
                       const float* __restrict__ Wrel, const float* __restrict__ Wroot) {
    int i = blockIdx.x * blockDim.x + threadIdx.x;
    if (i < SPLITX) {
        g_x16[i] = __float2half(x[i]);
        return;
    }
    i -= SPLITX;
    if (i < SPLITW) {
        int w = i >> 18;
        int off = i & (MM - 1);
        const float* src;
        if (w == 0) src = Wpr + off;
        else if (w == 1) src = Wpw + off;
        else if (w < 5) src = Wrel + (size_t)(w - 2) * MM + off;
        else src = Wroot + (size_t)(w - 5) * MM + off;
        g_w[i] = __float2half(*src);
        return;
    }
    i -= SPLITW;
    if (i < PADSZ) {
        int off = NN * HH + i;
        __half z = __float2half(0.0f);
        g_x16[off] = z;
        g_h16[off] = z;
        g_a16[off] = z;
        return;
    }
    i -= PADSZ;
    if (i < HH) { g_sum[i] = 0.f; g_sq[i] = 0.f; }
}

// ---------------- CSR build ----------------
__global__ void k_deg(const int* __restrict__ ei) {
    int e = blockIdx.x * blockDim.x + threadIdx.x;
    if (e < EE) atomicAdd(&g_degi[ei[EE + e]], 1);
}
__global__ void k_scanscale() {
    __shared__ int warp_part[32];
    __shared__ int carry;
    int t = threadIdx.x;
    int lane = t & 31, w = t >> 5;
    if (t == 0) carry = 0;
    __syncthreads();
    for (int base = 0; base < NN; base += 1024) {
        int i = base + t;
        int v = (i < NN) ? g_degi[i] : 0;
        if (i < NN) g_scale[i] = 1.0f / (float)(v > 0 ? v : 1);
        int s = v;
#pragma unroll
        for (int o = 1; o < 32; o <<= 1) {
            int u = __shfl_up_sync(0xffffffff, s, o);
            if (lane >= o) s += u;
        }
        if (lane == 31) warp_part[w] = s;
        __syncthreads();
        if (w == 0) {
            int p = warp_part[lane];
#pragma unroll
            for (int o = 1; o < 32; o <<= 1) {
                int u = __shfl_up_sync(0xffffffff, p, o);
                if (lane >= o) p += u;
            }
            warp_part[lane] = p;
        }
        __syncthreads();
        int add = (w > 0) ? warp_part[w - 1] : 0;
        int inc = s + add + carry;
        if (i < NN) g_rowptr[i + 1] = inc;
        __syncthreads();
        if (t == 1023) carry = inc;
        __syncthreads();
    }
    if (t == 0) g_rowptr[0] = 0;
}
__global__ void k_fill(const int* __restrict__ ei) {
    int e = blockIdx.x * blockDim.x + threadIdx.x;
    if (e < EE) {
        int dst = ei[EE + e];
        int pos = g_rowptr[dst] + atomicAdd(&g_fill[dst], 1);
        g_esrc[pos] = ei[e];
    }
}

// ---------------- fp16 mean aggregation + optional BN affine ----------------
__global__ void k_agg3(const __half* __restrict__ z, int useBN,
                       __half* __restrict__ oh, float* __restrict__ of) {
    int node = blockIdx.x;
    int t = threadIdx.x;                   // 0..127, 4 halves each
    if (t == 0) { g_degi[node] = 0; g_fill[node] = 0; }   // reset for next replay
    int s = g_rowptr[node];
    int e = g_rowptr[node + 1];
    float ax = 0.f, ay = 0.f, az = 0.f, aw = 0.f;
    int j = s;
    for (; j + 1 < e; j += 2) {
        int s0 = g_esrc[j];
        int s1 = g_esrc[j + 1];
        uint2 r0 = ((const uint2*)(z + (size_t)s0 * HH))[t];
        uint2 r1 = ((const uint2*)(z + (size_t)s1 * HH))[t];
        float2 a0 = __half22float2(*(__half2*)&r0.x);
        float2 a1 = __half22float2(*(__half2*)&r0.y);
        float2 b0 = __half22float2(*(__half2*)&r1.x);
        float2 b1 = __half22float2(*(__half2*)&r1.y);
        ax += a0.x + b0.x; ay += a0.y + b0.y;
        az += a1.x + b1.x; aw += a1.y + b1.y;
    }
    if (j < e) {
        int s0 = g_esrc[j];
        uint2 r0 = ((const uint2*)(z + (size_t)s0 * HH))[t];
        float2 a0 = __half22float2(*(__half2*)&r0.x);
        float2 a1 = __half22float2(*(__half2*)&r0.y);
        ax += a0.x; ay += a0.y; az += a1.x; aw += a1.y;
    }
    float sc = g_scale[node];
    ax *= sc; ay *= sc; az *= sc; aw *= sc;
    if (useBN) {
        float4 a = ((const float4*)g_bnA)[t];
        float4 b = ((const float4*)g_bnB)[t];
        ax = ax * a.x + b.x; ay = ay * a.y + b.y;
        az = az * a.z + b.z; aw = aw * a.w + b.w;
    }
    if (of) {
        ((float4*)(of + (size_t)node * HH))[t] = make_float4(ax, ay, az, aw);
    }
    if (oh) {
        __half2* ph = (__half2*)(oh + (size_t)node * HH);
        ph[t * 2 + 0] = __halves2half2(__float2half(ax), __float2half(ay));
        ph[t * 2 + 1] = __halves2half2(__float2half(az), __float2half(aw));
    }
}

// ---------------- mma.sync dual GEMM, 96x128 tile, BK=32, fp16 ----------------
// acc += A@W^T. nk=32: dual (A1,W1 kt<16; A2,W2 kt>=16). nk=16: single pair.
// finalize=0: fp32 partial to Cpart. finalize=1: (+Cin) relu -> fp16 Z + BN stats.
#define LDS 40
#define A_HALVES (96 * LDS)                       // 3840
#define B_HALVES (128 * LDS)                      // 5120
#define STAGE_HALVES (A_HALVES + B_HALVES)        // 8960 halves = 17920 B
#define GEMM_SMEM (2 * STAGE_HALVES * 2)          // 35840 B

__global__ __launch_bounds__(192, 3)
void k_gemm8(const __half* __restrict__ a1, const __half* __restrict__ a2,
             const __half* __restrict__ w1, const __half* __restrict__ w2,
             float* __restrict__ Cpart, const float* __restrict__ Cin,
             __half* __restrict__ Z,
             int nk, int finalize) {
    extern __shared__ __half dsm[];

    const int tx = threadIdx.x;
    const int lane = tx & 31;
    const int warp = tx >> 5;
    const int wm = (warp % 3) * 32;
    const int wn = (warp / 3) * 64;
    const int m0 = blockIdx.y * 96;
    const int n0 = blockIdx.x * 128;

    float acc[2][8][4];
#pragma unroll
    for (int i = 0; i < 2; i++)
#pragma unroll
        for (int j = 0; j < 8; j++)
#pragma unroll
            for (int q = 0; q < 4; q++) acc[i][j][q] = 0.f;

    auto loadStage = [&](int kt, int st) {
        const __half* A = (kt < 16) ? a1 : a2;
        const __half* W = (kt < 16) ? w1 : w2;
        int k0 = (kt & 15) * 32;
        __half* base = dsm + st * STAGE_HALVES;
#pragma unroll
        for (int rep = 0; rep < 2; rep++) {
            int idx = tx + rep * 192;
            int row = idx >> 2;
            int seg = (idx & 3) * 8;
            size_t ao = (size_t)(m0 + row) * HH + k0 + seg;
            uint32_t so = (uint32_t)(row * LDS + seg);
            cpa16(cvta_s(base + so), A + ao);
        }
#pragma unroll
        for (int rep = 0; rep < 3; rep++) {
            int idx = tx + rep * 192;
            if (idx < 512) {
                int row = idx >> 2;
                int seg = (idx & 3) * 8;
                size_t wo = (size_t)(n0 + row) * HH + k0 + seg;
                uint32_t so = (uint32_t)(row * LDS + seg);
                cpa16(cvta_s(base + A_HALVES + so), W + wo);
            }
        }
        asm volatile("cp.async.commit_group;\n");
    };

    loadStage(0, 0);

    for (int kt = 0; kt < nk; ++kt) {
        int st = kt & 1;
        if (kt + 1 < nk) {
            loadStage(kt + 1, st ^ 1);
            asm volatile("cp.async.wait_group 1;\n" ::: "memory");
        } else {
            asm volatile("cp.async.wait_group 0;\n" ::: "memory");
        }
        __syncthreads();

        __half* base = dsm + st * STAGE_HALVES;
        __half* sA = base;
        __half* sW = base + A_HALVES;

#pragma unroll
        for (int ks = 0; ks < 2; ks++) {
            int kc = ks * 16;
            uint32_t ah[2][4];
#pragma unroll
            for (int i = 0; i < 2; i++) {
                int r = wm + i * 16 + (lane & 15);
                int c = kc + ((lane >> 4) & 1) * 8;
                ldm_x4(ah[i][0], ah[i][1], ah[i][2], ah[i][3], cvta_s(sA + r * LDS + c));
            }
#pragma unroll
            for (int jj = 0; jj < 4; jj++) {
                int r = wn + jj * 16 + (lane & 7) + ((lane >> 4) & 1) * 8;
                int c = kc + ((lane >> 3) & 1) * 8;
                uint32_t bh[4];
                ldm_x4(bh[0], bh[1], bh[2], bh[3], cvta_s(sW + r * LDS + c));
#pragma unroll
                for (int i = 0; i < 2; i++) {
                    mma_f16(acc[i][jj * 2 + 0], ah[i][0], ah[i][1], ah[i][2], ah[i][3], bh[0], bh[1]);
                    mma_f16(acc[i][jj * 2 + 1], ah[i][0], ah[i][1], ah[i][2], ah[i][3], bh[2], bh[3]);
                }
            }
        }
        __syncthreads();
    }

    if (!finalize) {
#pragma unroll
        for (int j = 0; j < 8; j++) {
#pragma unroll
            for (int i = 0; i < 2; i++) {
                int r = m0 + wm + i * 16 + (lane >> 2);
                int c = n0 + wn + j * 8 + (lane & 3) * 2;
                *(float2*)(Cpart + (size_t)r * HH + c) = make_float2(acc[i][j][0], acc[i][j][1]);
                *(float2*)(Cpart + (size_t)(r + 8) * HH + c) = make_float2(acc[i][j][2], acc[i][j][3]);
            }
        }
        return;
    }

    // finalize: (+Cin) + relu + fp16 store + fused BN column stats
#pragma unroll
    for (int j = 0; j < 8; j++) {
        float s0 = 0.f, s1 = 0.f, q0 = 0.f, q1 = 0.f;
#pragma unroll
        for (int i = 0; i < 2; i++) {
            int r = m0 + wm + i * 16 + (lane >> 2);
            int c = n0 + wn + j * 8 + (lane & 3) * 2;
            float v00 = acc[i][j][0], v01 = acc[i][j][1];
            float v10 = acc[i][j][2], v11 = acc[i][j][3];
            if (Cin) {
                float2 p0 = *(const float2*)(Cin + (size_t)r * HH + c);
                float2 p1 = *(const float2*)(Cin + (size_t)(r + 8) * HH + c);
                v00 += p0.x; v01 += p0.y; v10 += p1.x; v11 += p1.y;
            }
            v00 = fmaxf(v00, 0.f); v01 = fmaxf(v01, 0.f);
            v10 = fmaxf(v10, 0.f); v11 = fmaxf(v11, 0.f);
            *(__half2*)(Z + (size_t)r * HH + c) =
                __halves2half2(__float2half(v00), __float2half(v01));
            *(__half2*)(Z + (size_t)(r + 8) * HH + c) =
                __halves2half2(__float2half(v10), __float2half(v11));
            s0 += v00 + v10; s1 += v01 + v11;
            q0 += v00 * v00 + v10 * v10; q1 += v01 * v01 + v11 * v11;
        }
#pragma unroll
        for (int o = 16; o >= 4; o >>= 1) {
            s0 += __shfl_down_sync(0xffffffff, s0, o);
            s1 += __shfl_down_sync(0xffffffff, s1, o);
            q0 += __shfl_down_sync(0xffffffff, q0, o);
            q1 += __shfl_down_sync(0xffffffff, q1, o);
        }
        if (lane < 4) {
            int cc = n0 + wn + j * 8 + lane * 2;
            atomicAdd(&g_sum[cc], s0);
            atomicAdd(&g_sum[cc + 1], s1);
            atomicAdd(&g_sq[cc], q0);
            atomicAdd(&g_sq[cc + 1], q1);
        }
    }
}

// ---------------- BatchNorm finalize (reads + self-zeroes stats) ----------------
__global__ void k_bnfin(const float* __restrict__ gamma, const float* __restrict__ beta) {
    int f = threadIdx.x;
    float s = g_sum[f];
    float q = g_sq[f];
    g_sum[f] = 0.f;
    g_sq[f] = 0.f;
    float mu = s / (float)NN;
    float var = q / (float)NN - mu * mu;
    float inv = rsqrtf(var + BN_EPS);
    float sc = gamma[f] * inv;
    g_bnA[f] = sc;
    g_bnB[f] = beta[f] - mu * sc;
}
// BN apply on fp16 z -> fp16 BN'd root operand
__global__ void k_bnapply3(const __half* __restrict__ z, __half* __restrict__ hh) {
    int idx = blockIdx.x * blockDim.x + threadIdx.x;   // over NN*HH/4
    if (idx >= NN * HH / 4) return;
    int f4 = idx & (HH / 4 - 1);
    uint2 raw = ((const uint2*)z)[idx];
    float2 v0 = __half22float2(*(__half2*)&raw.x);
    float2 v1 = __half22float2(*(__half2*)&raw.y);
    float4 a = ((const float4*)g_bnA)[f4];
    float4 b = ((const float4*)g_bnB)[f4];
    v0.x = v0.x * a.x + b.x;
    v0.y = v0.y * a.y + b.y;
    v1.x = v1.x * a.z + b.z;
    v1.y = v1.y * a.w + b.w;
    ((__half2*)hh)[idx * 2 + 0] = __halves2half2(__float2half(v0.x), __float2half(v0.y));
    ((__half2*)hh)[idx * 2 + 1] = __halves2half2(__float2half(v1.x), __float2half(v1.y));
}

// ---------------- final conv (C=10) + log_softmax ----------------
__global__ __launch_bounds__(320)
void k_final(const float* __restrict__ agg, const __half* __restrict__ r,
             const float* __restrict__ Wr, const float* __restrict__ Ww,
             float* __restrict__ out) {
    __shared__ float sa[HH];
    __shared__ float sh[HH];
    __shared__ float slog[CC];
    __shared__ float sLse;
    int node = blockIdx.x;
    int t = threadIdx.x;
    for (int i = t; i < HH; i += 320) {
        sa[i] = agg[(size_t)node * HH + i];
        sh[i] = __half2float(r[(size_t)node * HH + i]) * g_bnA[i] + g_bnB[i];
    }
    __syncthreads();
    int w = t >> 5, lane = t & 31;
    float s = 0.f;
    for (int k = lane; k < HH; k += 32)
        s += sa[k] * Wr[w * HH + k] + sh[k] * Ww[w * HH + k];
#pragma unroll
    for (int o = 16; o; o >>= 1) s += __shfl_down_sync(0xffffffff, s, o);
    if (lane == 0) slog[w] = s;
    __syncthreads();
    if (t == 0) {
        float mx = slog[0];
        for (int c = 1; c < CC; c++) mx = fmaxf(mx, slog[c]);
        float sum = 0.f;
        for (int c = 0; c < CC; c++) sum += expf(slog[c] - mx);
        sLse = mx + logf(sum);
    }
    __syncthreads();
    if (t < CC) out[(size_t)node * CC + t] = slog[t] - sLse;
}

// ---------------- launch ----------------
extern "C" void kernel_launch(void* const* d_in, const int* in_sizes, int n_in,
                              void* d_out, int out_size) {
    const float* x     = (const float*)d_in[0];
    const int*   ei    = (const int*)d_in[1];
    const float* Wpr   = (const float*)d_in[2];
    const float* Wpw   = (const float*)d_in[3];
    const float* Wrel  = (const float*)d_in[4];
    const float* Wroot = (const float*)d_in[5];
    const float* gamma = (const float*)d_in[6];
    const float* beta  = (const float*)d_in[7];
    const float* Wfr   = (const float*)d_in[8];
    const float* Wfw   = (const float*)d_in[9];
    float* out = (float*)d_out;

    static float *p_part = nullptr, *p_agg = nullptr;
    static __half *p_z1, *p_z2, *p_x16, *p_h16, *p_a16, *p_w;
    if (!p_part) {
        cudaGetSymbolAddress((void**)&p_part, g_part);
        cudaGetSymbolAddress((void**)&p_agg, g_agg);
        cudaGetSymbolAddress((void**)&p_z1, g_z1);
        cudaGetSymbolAddress((void**)&p_z2, g_z2);
        cudaGetSymbolAddress((void**)&p_x16, g_x16);
        cudaGetSymbolAddress((void**)&p_h16, g_h16);
        cudaGetSymbolAddress((void**)&p_a16, g_a16);
        cudaGetSymbolAddress((void**)&p_w, g_w);
        cudaFuncSetAttribute(k_gemm8, cudaFuncAttributeMaxDynamicSharedMemorySize, GEMM_SMEM);
    }

    dim3 gemmGrid(HH / 128, NP / 96);   // (4, 106) = 424 CTAs
    int eb = (EE + 255) / 256;
    int apb = (NN * HH / 4 + 255) / 256;
    int prepb = (PREP_TOTAL + 255) / 256;

    // 1: deg, 2: prep, 3: scan+scale, 4: GEMM(root half of proj) <- profiled window
    k_deg<<<eb, 256>>>(ei);
    k_prep<<<prepb, 256>>>(x, Wpr, Wpw, Wrel, Wroot);
    k_scanscale<<<1, 1024>>>();
    k_gemm8<<<gemmGrid, 192, GEMM_SMEM>>>(p_x16, p_x16,
                                          p_w + 1 * MM, p_w + 1 * MM,
                                          p_part, nullptr, nullptr, 16, 0);  // x@Wpw^T
    // 5: fill, 6: agg(x fp16), 7: GEMM(rel half, finalize -> z1 fp16 + stats)
    k_fill<<<eb, 256>>>(ei);
    k_agg3<<<NN, 128>>>(p_x16, 0, p_a16, nullptr);
    k_gemm8<<<gemmGrid, 192, GEMM_SMEM>>>(p_a16, p_a16,
                                          p_w + 0 * MM, p_w + 0 * MM,
                                          nullptr, p_part, p_z1, 16, 1);
    k_bnfin<<<1, HH>>>(gamma, beta);
    k_bnapply3<<<apb, 256>>>(p_z1, p_h16);

    __half* cur = p_z1;
    __half* nxt = p_z2;
    for (int l = 0; l < 3; ++l) {
        k_agg3<<<NN, 128>>>(cur, 1, p_a16, nullptr);
        k_gemm8<<<gemmGrid, 192, GEMM_SMEM>>>(p_a16, p_h16,
                                              p_w + (2 + l) * MM, p_w + (5 + l) * MM,
                                              nullptr, nullptr, nxt, 32, 1);
        k_bnfin<<<1, HH>>>(gamma + (size_t)(l + 1) * HH, beta + (size_t)(l + 1) * HH);
        if (l < 2)
            k_bnapply3<<<apb, 256>>>(nxt, p_h16);
        __half* tmp = cur; cur = nxt; nxt = tmp;
    }

    // final conv + log_softmax
    k_agg3<<<NN, 128>>>(cur, 1, nullptr, p_agg);
    k_final<<<NN, 320>>>(p_agg, cur, Wfr, Wfw, out);
}